// round 7
// baseline (speedup 1.0000x reference)
#include <cuda_runtime.h>
#include <cstdint>

#define TOK   4096
#define DIMN  512
#define GQ    32
#define HD    16
#define RNUM  4
#define INTER 405
#define INTP  408
#define DIN1  144
#define H1LD  576
#define HSLD  1620
#define NSEQ  512
#define ATT_SCALE 0.25f

// ---------------- device scratch (all tf32-rounded payloads) ----------------
__device__ float g_qkv[3 * TOK * DIMN];
__device__ float g_h1[TOK * H1LD];
__device__ float g_hs[TOK * HSLD];
__device__ float g_xc[TOK * DIMN];
__device__ float g_wqc[DIMN * DIMN];
__device__ float g_wkc[DIMN * DIMN];
__device__ float g_wvc[DIMN * DIMN];
__device__ float g_winc[DIMN * 64];
__device__ float g_w2c[HSLD * DIMN];
__device__ float g_w1c[RNUM * DIN1 * INTP];

// ---------------- helpers ----------------
__device__ __forceinline__ uint32_t smem_u32(const void* p) {
    uint32_t a;
    asm("{ .reg .u64 t; cvta.to.shared.u64 t, %1; cvt.u32.u64 %0, t; }"
        : "=r"(a) : "l"(p));
    return a;
}
__device__ __forceinline__ uint32_t f2tf32(float x) {
    uint32_t r;
    asm("cvt.rna.tf32.f32 %0, %1;" : "=r"(r) : "f"(x));
    return r;
}
__device__ __forceinline__ float tfr(float x) { return __uint_as_float(f2tf32(x)); }

__device__ __forceinline__ void cp16(uint32_t dst, const void* src, bool pred) {
    int sz = pred ? 16 : 0;
    asm volatile("cp.async.ca.shared.global [%0], [%1], 16, %2;"
                 :: "r"(dst), "l"(src), "r"(sz) : "memory");
}
#define CP_COMMIT() asm volatile("cp.async.commit_group;" ::: "memory")
#define CP_WAIT1()  asm volatile("cp.async.wait_group 1;" ::: "memory")
#define CP_WAIT0()  asm volatile("cp.async.wait_group 0;" ::: "memory")

__device__ __forceinline__ void mma_tf32_16x8x8(float d[4], const uint32_t a[4],
                                                const uint32_t b[2]) {
    asm volatile(
        "mma.sync.aligned.m16n8k8.row.col.f32.tf32.tf32.f32 "
        "{%0,%1,%2,%3}, {%4,%5,%6,%7}, {%8,%9}, {%0,%1,%2,%3};"
        : "+f"(d[0]), "+f"(d[1]), "+f"(d[2]), "+f"(d[3])
        : "r"(a[0]), "r"(a[1]), "r"(a[2]), "r"(a[3]), "r"(b[0]), "r"(b[1]));
}

// FFMA-pipe exp
__device__ __forceinline__ float fast_exp(float s) {
    s = fminf(fmaxf(s, -80.0f), 80.0f);
    float n = rintf(s * 1.4426950408889634f);
    float f = fmaf(n, -0.6931471805599453f, s);
    float p = 1.3888888889e-3f;
    p = fmaf(p, f, 8.3333333333e-3f);
    p = fmaf(p, f, 4.1666666667e-2f);
    p = fmaf(p, f, 1.6666666667e-1f);
    p = fmaf(p, f, 0.5f);
    p = fmaf(p, f, 1.0f);
    p = fmaf(p, f, 1.0f);
    int e = (int)n;
    return p * __int_as_float((e + 127) << 23);
}

// ---------------- one-pass tf32 conversion of x + all weights ----------------
#define C_X   2097152
#define C_WQ  (C_X + 262144)
#define C_WK  (C_WQ + 262144)
#define C_WV  (C_WK + 262144)
#define C_WIN (C_WV + 32768)
#define C_W2  (C_WIN + 829440)
#define C_W1  (C_W2 + 235008)   /* 576 * 408 */

__global__ void conv_all(const float* __restrict__ x,  const float* __restrict__ Wq,
                         const float* __restrict__ Wk, const float* __restrict__ Wv,
                         const float* __restrict__ Win, const float* __restrict__ W2,
                         const float* __restrict__ W1)
{
    int base = blockIdx.x * 1024 + threadIdx.x;
#pragma unroll
    for (int u = 0; u < 4; u++) {
        int i = base + u * 256;
        if (i < C_X)        g_xc[i] = tfr(x[i]);
        else if (i < C_WQ)  g_wqc[i - C_X]  = tfr(Wq[i - C_X]);
        else if (i < C_WK)  g_wkc[i - C_WQ] = tfr(Wk[i - C_WQ]);
        else if (i < C_WV)  g_wvc[i - C_WK] = tfr(Wv[i - C_WK]);
        else if (i < C_WIN) g_winc[i - C_WV] = tfr(Win[i - C_WV]);
        else if (i < C_W2)  g_w2c[i - C_WIN] = tfr(W2[i - C_WIN]);
        else if (i < C_W1) {
            int t = i - C_W2;
            int rk = t / INTP, n = t - rk * INTP;
            g_w1c[t] = (n < INTER) ? tfr(W1[rk * INTER + n]) : 0.f;
        }
    }
}

// ============================================================
// tf32 mma GEMM, CTA 128x128, KC=32, 8 warps, warp tile 32x64,
// 3-stage cp.async ring (race-free: wait -> barrier -> issue -> compute).
//   MODE 0: z=0,1,2 -> q/k/v (N=512); z=3 -> in_proj (N=64, bx==0 only)
//   MODE 2: MLP1 per rule z, B padded to 408 cols, K=144
//   MODE 3: MLP2 flat, K=1620 (+sum_r rs*b2 -> out) + rs tail copy
// ============================================================
#define KC     32
#define LDA    36
#define LDB    132
#define ABUF   (128 * LDA)
#define BBUF   (KC * LDB)
#define BUFSZ  (ABUF + BBUF)
#define NSTAGE 3
#define GEMM_SMEM (NSTAGE * BUFSZ * 4)

template<int MODE>
__global__ void __launch_bounds__(256, 2) mma_gemm(
    const float* __restrict__ bq, const float* __restrict__ bk,
    const float* __restrict__ bv, const float* __restrict__ b_in,
    const float* __restrict__ b1, const float* __restrict__ b2,
    const float* __restrict__ rs, float* __restrict__ out)
{
    extern __shared__ float dynsm[];
    const uint32_t smbase = smem_u32(dynsm);

    const int tid = threadIdx.x;
    const int wid = tid >> 5, lane = tid & 31;
    const int wm = wid >> 1, wn = wid & 1;
    const int g = lane >> 2, tq = lane & 3;
    const int m_base = blockIdx.y * 128;
    const int n_base = blockIdx.x * 128;
    const int z = blockIdx.z;

    const float* A; const float* B; const float* bias;
    int lda, K, NB;
    if (MODE == 0) {
        A = g_xc + (size_t)m_base * DIMN; lda = DIMN; K = DIMN;
        if (z == 3) {
            if (blockIdx.x != 0) return;
            B = g_winc; NB = 64; bias = b_in;
        } else {
            B = (z == 0) ? g_wqc : (z == 1) ? g_wkc : g_wvc; NB = DIMN;
            bias = (z == 0) ? bq : (z == 1) ? bk : bv;
        }
    }
    if (MODE == 2) {
        A = g_h1 + (size_t)m_base * H1LD + z * DIN1; lda = H1LD; K = DIN1;
        B = g_w1c + (size_t)z * DIN1 * INTP; NB = INTP; bias = b1 + z * INTER;
    }
    if (MODE == 3) {
        A = g_hs + (size_t)m_base * HSLD; lda = HSLD; K = HSLD;
        B = g_w2c; NB = DIMN; bias = b2;
    }

    float d[2][8][4];
#pragma unroll
    for (int i = 0; i < 2; i++)
#pragma unroll
        for (int j = 0; j < 8; j++)
#pragma unroll
            for (int c = 0; c < 4; c++) d[i][j][c] = 0.f;

    const int KT = (K + KC - 1) / KC;

    const int ar = tid >> 3;
    const int ac = (tid & 7) * 4;
    const int br = tid >> 5;
    const int bc = (tid & 31) * 4;
    const bool bn_ok = (n_base + bc) < NB;

#define ISSUE(k0, buf)                                                         \
    do {                                                                       \
        uint32_t sA = smbase + (uint32_t)((buf) * BUFSZ) * 4u;                 \
        uint32_t sB = sA + (uint32_t)ABUF * 4u;                                \
        _Pragma("unroll")                                                      \
        for (int i = 0; i < 4; i++) {                                          \
            int k = (k0) + ac;                                                 \
            bool p = k < K;                                                    \
            int kcl = p ? k : 0;                                               \
            cp16(sA + (uint32_t)((ar + 32 * i) * LDA + ac) * 4u,               \
                 A + (size_t)(ar + 32 * i) * lda + kcl, p);                    \
        }                                                                      \
        _Pragma("unroll")                                                      \
        for (int i = 0; i < 4; i++) {                                          \
            int kk = (k0) + br + 8 * i;                                        \
            bool p = (kk < K) && bn_ok;                                        \
            int kcl = (kk < K) ? kk : 0;                                       \
            cp16(sB + (uint32_t)((br + 8 * i) * LDB + bc) * 4u,                \
                 B + (size_t)kcl * NB + n_base + bc, p);                       \
        }                                                                      \
    } while (0)

    ISSUE(0, 0);
    CP_COMMIT();
    if (KT > 1) { ISSUE(KC, 1); CP_COMMIT(); }

    int ci = 0;          // compute buffer
    int ii = 2;          // next issue buffer

    for (int t = 0; t < KT; t++) {
        if (t + 1 < KT) CP_WAIT1(); else CP_WAIT0();
        __syncthreads();                 // separates prior readers from new writes
        if (t + 2 < KT) {
            ISSUE((t + 2) * KC, ii);
            CP_COMMIT();
            ii = (ii == NSTAGE - 1) ? 0 : ii + 1;
        }

        const float* As_ = dynsm + ci * BUFSZ;
        const float* Bs_ = As_ + ABUF;
        ci = (ci == NSTAGE - 1) ? 0 : ci + 1;
#pragma unroll
        for (int ks = 0; ks < 4; ks++) {
            const int kb = ks * 8 + tq;
            uint32_t bf[8][2];
#pragma unroll
            for (int j = 0; j < 8; j++) {
                int col = wn * 64 + j * 8 + g;
                bf[j][0] = __float_as_uint(Bs_[kb * LDB + col]);
                bf[j][1] = __float_as_uint(Bs_[(kb + 4) * LDB + col]);
            }
#pragma unroll
            for (int i = 0; i < 2; i++) {
                int r0 = wm * 32 + i * 16 + g;
                uint32_t af[4];
                af[0] = __float_as_uint(As_[r0 * LDA + kb]);
                af[1] = __float_as_uint(As_[(r0 + 8) * LDA + kb]);
                af[2] = __float_as_uint(As_[r0 * LDA + kb + 4]);
                af[3] = __float_as_uint(As_[(r0 + 8) * LDA + kb + 4]);
#pragma unroll
                for (int j = 0; j < 8; j++)
                    mma_tf32_16x8x8(d[i][j], af, bf[j]);
            }
        }
    }

    // ---------------- epilogue ----------------
#pragma unroll
    for (int i = 0; i < 2; i++) {
        int mr[2];
        mr[0] = m_base + wm * 32 + i * 16 + g;
        mr[1] = mr[0] + 8;
#pragma unroll
        for (int j = 0; j < 8; j++) {
            int n0 = n_base + wn * 64 + j * 8 + tq * 2;
#pragma unroll
            for (int rr = 0; rr < 2; rr++) {
                float v0 = d[i][j][rr * 2 + 0];
                float v1 = d[i][j][rr * 2 + 1];
                int m = mr[rr];
                if (MODE == 0) {
                    if (z == 3) {
                        if (n0 < 64) {
                            int r0i = n0 >> 4, d0i = n0 & 15;
                            int r1i = (n0 + 1) >> 4, d1i = (n0 + 1) & 15;
                            g_h1[(size_t)m * H1LD + r0i * DIN1 + 128 + d0i] =
                                tfr(v0 + b_in[n0]);
                            g_h1[(size_t)m * H1LD + r1i * DIN1 + 128 + d1i] =
                                tfr(v1 + b_in[n0 + 1]);
                        }
                    } else {
                        float* C = g_qkv + (size_t)z * TOK * DIMN;
                        *(float2*)(C + (size_t)m * DIMN + n0) =
                            make_float2(tfr(v0 + bias[n0]), tfr(v1 + bias[n0 + 1]));
                    }
                } else if (MODE == 2) {
                    float rsv = rs[m * RNUM + z];
                    if (n0 < INTER)
                        g_hs[(size_t)m * HSLD + z * INTER + n0] =
                            tfr(fmaxf(v0 + bias[n0], 0.f) * rsv);
                    if (n0 + 1 < INTER)
                        g_hs[(size_t)m * HSLD + z * INTER + n0 + 1] =
                            tfr(fmaxf(v1 + bias[n0 + 1], 0.f) * rsv);
                } else {
                    float4 q = *(const float4*)(rs + m * RNUM);
                    float b0 = q.x * bias[n0]            + q.y * bias[DIMN + n0]
                             + q.z * bias[2 * DIMN + n0] + q.w * bias[3 * DIMN + n0];
                    float b1v = q.x * bias[n0 + 1]            + q.y * bias[DIMN + n0 + 1]
                              + q.z * bias[2 * DIMN + n0 + 1] + q.w * bias[3 * DIMN + n0 + 1];
                    *(float2*)(out + (size_t)m * DIMN + n0) =
                        make_float2(v0 + b0, v1 + b1v);
                }
            }
        }
    }

    // rs tail copy folded into MLP2 (replaces memcpy node)
    if (MODE == 3 && blockIdx.x == 0) {
        int idx = blockIdx.y * 512 + tid * 2;
        *(float2*)(out + (size_t)TOK * DIMN + idx) = *(const float2*)(rs + idx);
    }
#undef ISSUE
}

// ============================================================
// Flash-style tensor-core attention (unchanged).
// ============================================================
#define LDQ 20
#define LDP 132
#define FA_SMEM ((2560 * 2 + 16 * LDP + 128 * LDP) * 4)

__global__ void __launch_bounds__(256, 2) fa_kernel()
{
    extern __shared__ float fs[];
    float* Qs = fs;
    float* Ks = fs + 128 * LDQ;
    float* Vs = fs + 2 * 128 * LDQ;
    float* Ps = Vs + 16 * LDP;

    const int qt = blockIdx.x;
    const int gg = blockIdx.y;
    const int bb = blockIdx.z;
    const int r = gg >> 3, hh = gg & 7;
    const int tid = threadIdx.x;
    const int wid = tid >> 5, lane = tid & 31;
    const int g = lane >> 2, tq = lane & 3;

    const float* gq = g_qkv;
    const float* gk = g_qkv + (size_t)TOK * DIMN;
    const float* gv = g_qkv + 2 * (size_t)TOK * DIMN;
    const int seq0 = bb * NSEQ;

    {
        int row = tid >> 1, half = tid & 1;
        int tok = seq0 + qt * 128 + row;
        const float4* src = (const float4*)(gq + (size_t)tok * DIMN + gg * HD + half * 8);
        float4 v0 = src[0], v1 = src[1];
        float* dst = Qs + row * LDQ + half * 8;
        dst[0] = v0.x * ATT_SCALE; dst[1] = v0.y * ATT_SCALE;
        dst[2] = v0.z * ATT_SCALE; dst[3] = v0.w * ATT_SCALE;
        dst[4] = v1.x * ATT_SCALE; dst[5] = v1.y * ATT_SCALE;
        dst[6] = v1.z * ATT_SCALE; dst[7] = v1.w * ATT_SCALE;
    }

    float o[2][4];
#pragma unroll
    for (int j = 0; j < 2; j++)
#pragma unroll
        for (int c = 0; c < 4; c++) o[j][c] = 0.f;
    float lsum[2] = {0.f, 0.f};

    const int row0 = wid * 16 + g;

    for (int jt = 0; jt < 4; jt++) {
        {
            int row = tid >> 1, half = tid & 1;
            int tok = seq0 + jt * 128 + row;
            const float4* ksrc = (const float4*)(gk + (size_t)tok * DIMN + gg * HD + half * 8);
            float4 k0v = ksrc[0], k1v = ksrc[1];
            float* kd = Ks + row * LDQ + half * 8;
            kd[0] = k0v.x; kd[1] = k0v.y; kd[2] = k0v.z; kd[3] = k0v.w;
            kd[4] = k1v.x; kd[5] = k1v.y; kd[6] = k1v.z; kd[7] = k1v.w;
            const float4* vsrc = (const float4*)(gv + (size_t)tok * DIMN + gg * HD + half * 8);
            float4 v0v = vsrc[0], v1v = vsrc[1];
            int d0 = half * 8;
            Vs[(d0 + 0) * LDP + row] = v0v.x;
            Vs[(d0 + 1) * LDP + row] = v0v.y;
            Vs[(d0 + 2) * LDP + row] = v0v.z;
            Vs[(d0 + 3) * LDP + row] = v0v.w;
            Vs[(d0 + 4) * LDP + row] = v1v.x;
            Vs[(d0 + 5) * LDP + row] = v1v.y;
            Vs[(d0 + 6) * LDP + row] = v1v.z;
            Vs[(d0 + 7) * LDP + row] = v1v.w;
        }
        __syncthreads();

#pragma unroll
        for (int hn = 0; hn < 2; hn++) {
            float s[8][4];
#pragma unroll
            for (int jn = 0; jn < 8; jn++)
#pragma unroll
                for (int c = 0; c < 4; c++) s[jn][c] = 0.f;
#pragma unroll
            for (int ks = 0; ks < 2; ks++) {
                int kb = ks * 8 + tq;
                uint32_t af[4];
                af[0] = __float_as_uint(Qs[row0 * LDQ + kb]);
                af[1] = __float_as_uint(Qs[(row0 + 8) * LDQ + kb]);
                af[2] = __float_as_uint(Qs[row0 * LDQ + kb + 4]);
                af[3] = __float_as_uint(Qs[(row0 + 8) * LDQ + kb + 4]);
#pragma unroll
                for (int jn = 0; jn < 8; jn++) {
                    int col = hn * 64 + jn * 8 + g;
                    uint32_t bf[2];
                    bf[0] = __float_as_uint(Ks[col * LDQ + kb]);
                    bf[1] = __float_as_uint(Ks[col * LDQ + kb + 4]);
                    mma_tf32_16x8x8(s[jn], af, bf);
                }
            }
#pragma unroll
            for (int jn = 0; jn < 8; jn++) {
                int c0 = hn * 64 + jn * 8 + 2 * tq;
                int gc0 = jt * 128 + c0;
#pragma unroll
                for (int rr = 0; rr < 2; rr++) {
                    int rl = row0 + rr * 8;
                    int grow = qt * 128 + rl;
                    float p0 = fast_exp(s[jn][rr * 2 + 0]);
                    float p1 = fast_exp(s[jn][rr * 2 + 1]);
                    if (gc0 == grow)     p0 = 0.f;
                    if (gc0 + 1 == grow) p1 = 0.f;
                    lsum[rr] += p0 + p1;
                    float2 st = make_float2(tfr(p0), tfr(p1));
                    *(float2*)(Ps + rl * LDP + c0) = st;
                }
            }
        }
        __syncthreads();

#pragma unroll
        for (int ksi = 0; ksi < 16; ksi++) {
            int kb = ksi * 8 + tq;
            uint32_t af[4];
            af[0] = __float_as_uint(Ps[row0 * LDP + kb]);
            af[1] = __float_as_uint(Ps[(row0 + 8) * LDP + kb]);
            af[2] = __float_as_uint(Ps[row0 * LDP + kb + 4]);
            af[3] = __float_as_uint(Ps[(row0 + 8) * LDP + kb + 4]);
#pragma unroll
            for (int jn = 0; jn < 2; jn++) {
                int col = jn * 8 + g;
                uint32_t bf[2];
                bf[0] = __float_as_uint(Vs[col * LDP + kb]);
                bf[1] = __float_as_uint(Vs[col * LDP + kb + 4]);
                mma_tf32_16x8x8(o[jn], af, bf);
            }
        }
        __syncthreads();
    }

#pragma unroll
    for (int rr = 0; rr < 2; rr++) {
        lsum[rr] += __shfl_xor_sync(0xFFFFFFFF, lsum[rr], 1);
        lsum[rr] += __shfl_xor_sync(0xFFFFFFFF, lsum[rr], 2);
    }
    float inv[2] = {1.f / lsum[0], 1.f / lsum[1]};

#pragma unroll
    for (int rr = 0; rr < 2; rr++) {
        int tok = seq0 + qt * 128 + row0 + rr * 8;
        float* dst = g_h1 + (size_t)tok * H1LD + r * DIN1 + hh * HD;
#pragma unroll
        for (int jn = 0; jn < 2; jn++) {
            int col = jn * 8 + 2 * tq;
            *(float2*)(dst + col) = make_float2(tfr(o[jn][rr * 2 + 0] * inv[rr]),
                                                tfr(o[jn][rr * 2 + 1] * inv[rr]));
        }
    }
}

// ============================================================
extern "C" void kernel_launch(void* const* d_in, const int* in_sizes, int n_in,
                              void* d_out, int out_size)
{
    const float* x    = (const float*)d_in[0];
    const float* rs   = (const float*)d_in[1];
    const float* Wq   = (const float*)d_in[2];
    const float* bq   = (const float*)d_in[3];
    const float* Wk   = (const float*)d_in[4];
    const float* bk   = (const float*)d_in[5];
    const float* Wv   = (const float*)d_in[6];
    const float* bv   = (const float*)d_in[7];
    const float* Win  = (const float*)d_in[8];
    const float* b_in = (const float*)d_in[9];
    const float* W1   = (const float*)d_in[10];
    const float* b1   = (const float*)d_in[11];
    const float* W2   = (const float*)d_in[12];
    const float* b2   = (const float*)d_in[13];
    float* out = (float*)d_out;

    cudaFuncSetAttribute(mma_gemm<0>, cudaFuncAttributeMaxDynamicSharedMemorySize, GEMM_SMEM);
    cudaFuncSetAttribute(mma_gemm<2>, cudaFuncAttributeMaxDynamicSharedMemorySize, GEMM_SMEM);
    cudaFuncSetAttribute(mma_gemm<3>, cudaFuncAttributeMaxDynamicSharedMemorySize, GEMM_SMEM);
    cudaFuncSetAttribute(fa_kernel, cudaFuncAttributeMaxDynamicSharedMemorySize, FA_SMEM);

    conv_all<<<(C_W1 + 1023) / 1024, 256>>>(x, Wq, Wk, Wv, Win, W2, W1);

    mma_gemm<0><<<dim3(4, 32, 4), 256, GEMM_SMEM>>>(bq, bk, bv, b_in, b1, b2, rs, out);
    fa_kernel<<<dim3(4, GQ, 8), 256, FA_SMEM>>>();
    mma_gemm<2><<<dim3(4, 32, 4), 256, GEMM_SMEM>>>(bq, bk, bv, b_in, b1, b2, rs, out);
    mma_gemm<3><<<dim3(4, 32, 1), 256, GEMM_SMEM>>>(bq, bk, bv, b_in, b1, b2, rs, out);
}

// round 8
// speedup vs baseline: 1.7440x; 1.7440x over previous
#include <cuda_runtime.h>
#include <cuda_fp16.h>
#include <cstdint>

#define TOK   4096
#define DIMN  512
#define GQ    32
#define HD    16
#define RNUM  4
#define INTER 405
#define INTP  408
#define DIN1  144
#define H1LD  576
#define HSLDP 1632
#define NSEQ  512

// ---------------- device scratch (fp16 payloads) ----------------
__device__ __half g_xc[TOK * DIMN];
__device__ __half g_wqt[DIMN * DIMN];     // [n][k]
__device__ __half g_wkt[DIMN * DIMN];
__device__ __half g_wvt[DIMN * DIMN];
__device__ __half g_wint[64 * DIMN];
__device__ __half g_w1t[RNUM * INTP * DIN1];   // per rule [408][144], pad rows zero
__device__ __half g_w2t[DIMN * HSLDP];         // [512][1632], pad k zero
__device__ __half g_qkv[3 * TOK * DIMN];
__device__ __half g_h1[TOK * H1LD];
__device__ __half g_hs[TOK * HSLDP];           // per rule stride 408, pads zero

// ---------------- helpers ----------------
__device__ __forceinline__ uint32_t smem_u32(const void* p) {
    uint32_t a;
    asm("{ .reg .u64 t; cvta.to.shared.u64 t, %1; cvt.u32.u64 %0, t; }"
        : "=r"(a) : "l"(p));
    return a;
}
__device__ __forceinline__ void cp16(uint32_t dst, const void* src, bool pred) {
    int sz = pred ? 16 : 0;
    asm volatile("cp.async.ca.shared.global [%0], [%1], 16, %2;"
                 :: "r"(dst), "l"(src), "r"(sz) : "memory");
}
#define CP_COMMIT() asm volatile("cp.async.commit_group;" ::: "memory")
#define CP_WAIT1()  asm volatile("cp.async.wait_group 1;" ::: "memory")
#define CP_WAIT0()  asm volatile("cp.async.wait_group 0;" ::: "memory")

__device__ __forceinline__ void mma_f16(float d[4], const uint32_t a[4],
                                        const uint32_t b[2]) {
    asm volatile(
        "mma.sync.aligned.m16n8k16.row.col.f32.f16.f16.f32 "
        "{%0,%1,%2,%3}, {%4,%5,%6,%7}, {%8,%9}, {%0,%1,%2,%3};"
        : "+f"(d[0]), "+f"(d[1]), "+f"(d[2]), "+f"(d[3])
        : "r"(a[0]), "r"(a[1]), "r"(a[2]), "r"(a[3]), "r"(b[0]), "r"(b[1]));
}

// FFMA-pipe exp
__device__ __forceinline__ float fast_exp(float s) {
    s = fminf(fmaxf(s, -80.0f), 80.0f);
    float n = rintf(s * 1.4426950408889634f);
    float f = fmaf(n, -0.6931471805599453f, s);
    float p = 1.3888888889e-3f;
    p = fmaf(p, f, 8.3333333333e-3f);
    p = fmaf(p, f, 4.1666666667e-2f);
    p = fmaf(p, f, 1.6666666667e-1f);
    p = fmaf(p, f, 0.5f);
    p = fmaf(p, f, 1.0f);
    p = fmaf(p, f, 1.0f);
    int e = (int)n;
    return p * __int_as_float((e + 127) << 23);
}

// ---------------- one-shot conversion + weight transposes ----------------
__device__ void trans_tile(const float* __restrict__ src, __half* __restrict__ dst,
                           int K, int N, int ldk, int tk, int tn, bool w2remap)
{
    __shared__ float tl[32][33];
    int tx = threadIdx.x & 31, ty = threadIdx.x >> 5;   // 32 x 8
    int k0 = tk * 32, n0 = tn * 32;
#pragma unroll
    for (int i = 0; i < 4; i++) {
        int k = k0 + ty + i * 8, n = n0 + tx;
        tl[ty + i * 8][tx] = (k < K && n < N) ? src[(size_t)k * N + n] : 0.f;
    }
    __syncthreads();
#pragma unroll
    for (int i = 0; i < 4; i++) {
        int n = n0 + ty + i * 8, k = k0 + tx;
        if (n < N && k < K) {
            int kk = w2remap ? k + 3 * (k / 405) : k;
            dst[(size_t)n * ldk + kk] = __float2half_rn(tl[tx][ty + i * 8]);
        }
    }
}

__global__ void conv_all(const float* __restrict__ x,  const float* __restrict__ Wq,
                         const float* __restrict__ Wk, const float* __restrict__ Wv,
                         const float* __restrict__ Win, const float* __restrict__ W1,
                         const float* __restrict__ W2)
{
    int b = blockIdx.x;
    if (b < 256) {
#pragma unroll
        for (int u = 0; u < 32; u++) {
            int i = b * 8192 + u * 256 + threadIdx.x;
            g_xc[i] = __float2half_rn(x[i]);
        }
    } else if (b < 512) {
        int i = b - 256;  trans_tile(Wq, g_wqt, 512, 512, 512, i / 16, i % 16, false);
    } else if (b < 768) {
        int i = b - 512;  trans_tile(Wk, g_wkt, 512, 512, 512, i / 16, i % 16, false);
    } else if (b < 1024) {
        int i = b - 768;  trans_tile(Wv, g_wvt, 512, 512, 512, i / 16, i % 16, false);
    } else if (b < 1056) {
        int i = b - 1024; trans_tile(Win, g_wint, 512, 64, 512, i / 2, i % 2, false);
    } else if (b < 1316) {
        int i = b - 1056; int r = i / 65, rem = i % 65;
        trans_tile(W1 + (size_t)r * DIN1 * INTER, g_w1t + (size_t)r * INTP * DIN1,
                   DIN1, INTER, DIN1, rem / 13, rem % 13, false);
    } else {
        int i = b - 1316;
        trans_tile(W2, g_w2t, 1620, 512, HSLDP, i / 16, i % 16, true);
    }
}

// ============================================================
// fp16 mma GEMM, CTA 128x128, KC=32, 8 warps, warp tile 32x64,
// 2-stage cp.async (race-free: wait -> compute -> barrier -> issue t+2).
// A [m][k] half, B transposed [n][k] half -> all fragment loads are
// contiguous 32-bit LDS.
//   MODE 0: z=0..2 q/k/v; z=3 in_proj (N=64, bx==0)
//   MODE 2: MLP1 per rule z (K=144, N=405, relu*rs+b1)
//   MODE 3: MLP2 (K=1632 padded, +sum_r rs*b2 -> out fp32) + rs tail
// ============================================================
#define KC     32
#define LDH    40                  /* halves per smem row (A and B) */
#define ABUFH  (128 * LDH)
#define BBUFH  (128 * LDH)
#define BUFH   (ABUFH + BBUFH)
#define GEMM_SMEM (2 * BUFH * 2)   /* bytes: 2 stages x BUFH halves */

template<int MODE>
__global__ void __launch_bounds__(256, 2) mma_gemm(
    const float* __restrict__ bq, const float* __restrict__ bk,
    const float* __restrict__ bv, const float* __restrict__ b_in,
    const float* __restrict__ b1, const float* __restrict__ b2,
    const float* __restrict__ rs, float* __restrict__ out)
{
    extern __shared__ __half dynsh[];
    const uint32_t smbase = smem_u32(dynsh);

    const int tid = threadIdx.x;
    const int wid = tid >> 5, lane = tid & 31;
    const int wm = wid >> 1, wn = wid & 1;
    const int g = lane >> 2, tq = lane & 3;
    const int m_base = blockIdx.y * 128;
    const int n_base = blockIdx.x * 128;
    const int z = blockIdx.z;

    const __half* A; const __half* Bt; const float* bias;
    int lda, K, Nrows, ldbk;
    if (MODE == 0) {
        A = g_xc + (size_t)m_base * DIMN; lda = DIMN; K = DIMN;
        if (z == 3) {
            if (blockIdx.x != 0) return;
            Bt = g_wint; Nrows = 64; ldbk = DIMN; bias = b_in;
        } else {
            Bt = (z == 0) ? g_wqt : (z == 1) ? g_wkt : g_wvt;
            Nrows = 512; ldbk = DIMN;
            bias = (z == 0) ? bq : (z == 1) ? bk : bv;
        }
    }
    if (MODE == 2) {
        A = g_h1 + (size_t)m_base * H1LD + z * DIN1; lda = H1LD; K = DIN1;
        Bt = g_w1t + (size_t)z * INTP * DIN1; Nrows = INTP; ldbk = DIN1;
        bias = b1 + z * INTER;
    }
    if (MODE == 3) {
        A = g_hs + (size_t)m_base * HSLDP; lda = HSLDP; K = HSLDP;
        Bt = g_w2t; Nrows = 512; ldbk = HSLDP; bias = b2;
    }

    float d[2][8][4];
#pragma unroll
    for (int i = 0; i < 2; i++)
#pragma unroll
        for (int j = 0; j < 8; j++)
#pragma unroll
            for (int c = 0; c < 4; c++) d[i][j][c] = 0.f;

    const int KT = (K + KC - 1) / KC;

    // loader: 128 rows x 32 halves = 512 x 16B chunks; 2 per thread for A, 2 for B
    const int lrow = tid >> 2;          // 0..63, +64 for second
    const int lkg  = tid & 3;           // 8-half group within chunk

#define ISSUE(k0, buf)                                                         \
    do {                                                                       \
        uint32_t sA = smbase + (uint32_t)((buf) * BUFH) * 2u;                  \
        uint32_t sB = sA + (uint32_t)ABUFH * 2u;                               \
        int kk = (k0) + lkg * 8;                                               \
        bool pk = kk < K;                                                      \
        int kcl = pk ? kk : 0;                                                 \
        _Pragma("unroll")                                                      \
        for (int i = 0; i < 2; i++) {                                          \
            int row = lrow + 64 * i;                                           \
            cp16(sA + (uint32_t)(row * LDH + lkg * 8) * 2u,                    \
                 A + (size_t)row * lda + kcl, pk);                             \
            bool pb = pk && (n_base + row) < Nrows;                            \
            int brow = ((n_base + row) < Nrows) ? (n_base + row) : 0;          \
            cp16(sB + (uint32_t)(row * LDH + lkg * 8) * 2u,                    \
                 Bt + (size_t)brow * ldbk + kcl, pb);                          \
        }                                                                      \
    } while (0)

    ISSUE(0, 0);
    CP_COMMIT();
    if (KT > 1) { ISSUE(KC, 1); CP_COMMIT(); }
    CP_WAIT1();
    __syncthreads();

    for (int t = 0; t < KT; t++) {
        const __half* As_ = dynsh + (t & 1) * BUFH;
        const __half* Bs_ = As_ + ABUFH;
#pragma unroll
        for (int ks = 0; ks < 2; ks++) {
            uint32_t bf[8][2];
#pragma unroll
            for (int j = 0; j < 8; j++) {
                int col = wn * 64 + j * 8 + g;
                bf[j][0] = *(const uint32_t*)(Bs_ + col * LDH + ks * 16 + 2 * tq);
                bf[j][1] = *(const uint32_t*)(Bs_ + col * LDH + ks * 16 + 8 + 2 * tq);
            }
#pragma unroll
            for (int i = 0; i < 2; i++) {
                int r0 = wm * 32 + i * 16 + g;
                uint32_t af[4];
                af[0] = *(const uint32_t*)(As_ + r0 * LDH + ks * 16 + 2 * tq);
                af[1] = *(const uint32_t*)(As_ + (r0 + 8) * LDH + ks * 16 + 2 * tq);
                af[2] = *(const uint32_t*)(As_ + r0 * LDH + ks * 16 + 8 + 2 * tq);
                af[3] = *(const uint32_t*)(As_ + (r0 + 8) * LDH + ks * 16 + 8 + 2 * tq);
#pragma unroll
                for (int j = 0; j < 8; j++)
                    mma_f16(d[i][j], af, bf[j]);
            }
        }
        __syncthreads();                       // all warps done reading buf t&1
        if (t + 2 < KT) { ISSUE((t + 2) * KC, t & 1); CP_COMMIT(); }
        if (t + 1 < KT) {
            if (t + 2 < KT) CP_WAIT1(); else CP_WAIT0();
            __syncthreads();                   // buf (t+1)&1 data visible
        }
    }

    // ---------------- epilogue ----------------
#pragma unroll
    for (int i = 0; i < 2; i++) {
        int mr[2];
        mr[0] = m_base + wm * 32 + i * 16 + g;
        mr[1] = mr[0] + 8;
#pragma unroll
        for (int j = 0; j < 8; j++) {
            int n0 = n_base + wn * 64 + j * 8 + tq * 2;
#pragma unroll
            for (int rr = 0; rr < 2; rr++) {
                float v0 = d[i][j][rr * 2 + 0];
                float v1 = d[i][j][rr * 2 + 1];
                int m = mr[rr];
                if (MODE == 0) {
                    if (z == 3) {
                        if (n0 < 64) {
                            int r0i = n0 >> 4, d0i = n0 & 15;
                            int r1i = (n0 + 1) >> 4, d1i = (n0 + 1) & 15;
                            g_h1[(size_t)m * H1LD + r0i * DIN1 + 128 + d0i] =
                                __float2half_rn(v0 + b_in[n0]);
                            g_h1[(size_t)m * H1LD + r1i * DIN1 + 128 + d1i] =
                                __float2half_rn(v1 + b_in[n0 + 1]);
                        }
                    } else {
                        __half* C = g_qkv + (size_t)z * TOK * DIMN;
                        *(__half2*)(C + (size_t)m * DIMN + n0) =
                            __floats2half2_rn(v0 + bias[n0], v1 + bias[n0 + 1]);
                    }
                } else if (MODE == 2) {
                    float rsv = rs[m * RNUM + z];
                    size_t base = (size_t)m * HSLDP + z * INTP + n0;
                    if (n0 + 1 < INTER) {
                        *(__half2*)(g_hs + base) = __floats2half2_rn(
                            fmaxf(v0 + bias[n0], 0.f) * rsv,
                            fmaxf(v1 + bias[n0 + 1], 0.f) * rsv);
                    } else if (n0 < INTER) {
                        g_hs[base] = __float2half_rn(fmaxf(v0 + bias[n0], 0.f) * rsv);
                    }
                } else {
                    float4 q = *(const float4*)(rs + m * RNUM);
                    float b0 = q.x * bias[n0]            + q.y * bias[DIMN + n0]
                             + q.z * bias[2 * DIMN + n0] + q.w * bias[3 * DIMN + n0];
                    float b1v = q.x * bias[n0 + 1]            + q.y * bias[DIMN + n0 + 1]
                              + q.z * bias[2 * DIMN + n0 + 1] + q.w * bias[3 * DIMN + n0 + 1];
                    *(float2*)(out + (size_t)m * DIMN + n0) =
                        make_float2(v0 + b0, v1 + b1v);
                }
            }
        }
    }

    if (MODE == 3 && blockIdx.x == 0) {
        int idx = blockIdx.y * 512 + tid * 2;
        *(float2*)(out + (size_t)TOK * DIMN + idx) = *(const float2*)(rs + idx);
    }
#undef ISSUE
}

// ============================================================
// Flash attention, fp16 mma (HD=16 => one k16 mma per S tile).
// ============================================================
#define LDQH 24
#define LDPH 136
#define FA_SMEM ((128 * LDQH * 2 + 16 * LDPH + 128 * LDPH) * 2)

__global__ void __launch_bounds__(256, 2) fa_kernel()
{
    extern __shared__ __half fsh[];
    __half* Qs = fsh;                           // [128][24]
    __half* Ks = fsh + 128 * LDQH;              // [128][24]
    __half* Vs = fsh + 2 * 128 * LDQH;          // [16][136]
    __half* Ps = Vs + 16 * LDPH;                // [128][136]

    const int qt = blockIdx.x;
    const int gg = blockIdx.y;
    const int bb = blockIdx.z;
    const int r = gg >> 3, hh = gg & 7;
    const int tid = threadIdx.x;
    const int wid = tid >> 5, lane = tid & 31;
    const int g = lane >> 2, tq = lane & 3;

    const __half* gq = g_qkv;
    const __half* gk = g_qkv + (size_t)TOK * DIMN;
    const __half* gv = g_qkv + 2 * (size_t)TOK * DIMN;
    const int seq0 = bb * NSEQ;

    const __half2 qscale = __floats2half2_rn(0.25f, 0.25f);

    {   // Q tile
        int row = tid >> 1, part = tid & 1;
        int tok = seq0 + qt * 128 + row;
        uint4 v = *(const uint4*)(gq + (size_t)tok * DIMN + gg * HD + part * 8);
        __half2* pv = (__half2*)&v;
#pragma unroll
        for (int l = 0; l < 4; l++) pv[l] = __hmul2(pv[l], qscale);
        *(uint4*)(Qs + row * LDQH + part * 8) = v;
    }

    float o[2][4];
#pragma unroll
    for (int j = 0; j < 2; j++)
#pragma unroll
        for (int c = 0; c < 4; c++) o[j][c] = 0.f;
    float lsum[2] = {0.f, 0.f};

    const int row0 = wid * 16 + g;

    for (int jt = 0; jt < 4; jt++) {
        {   // K, V tiles
            int row = tid >> 1, part = tid & 1;
            int tok = seq0 + jt * 128 + row;
            uint4 kv = *(const uint4*)(gk + (size_t)tok * DIMN + gg * HD + part * 8);
            *(uint4*)(Ks + row * LDQH + part * 8) = kv;
            uint4 vv = *(const uint4*)(gv + (size_t)tok * DIMN + gg * HD + part * 8);
            __half tmp[8];
            *(uint4*)tmp = vv;
            int d0 = part * 8;
#pragma unroll
            for (int l = 0; l < 8; l++) Vs[(d0 + l) * LDPH + row] = tmp[l];
        }
        __syncthreads();

        // Q a-fragment (k = full 16, same for all columns)
        uint32_t af[4];
        af[0] = *(const uint32_t*)(Qs + row0 * LDQH + 2 * tq);
        af[1] = *(const uint32_t*)(Qs + (row0 + 8) * LDQH + 2 * tq);
        af[2] = *(const uint32_t*)(Qs + row0 * LDQH + 8 + 2 * tq);
        af[3] = *(const uint32_t*)(Qs + (row0 + 8) * LDQH + 8 + 2 * tq);

#pragma unroll
        for (int hn = 0; hn < 2; hn++) {
            float s[8][4];
#pragma unroll
            for (int jn = 0; jn < 8; jn++) {
#pragma unroll
                for (int c = 0; c < 4; c++) s[jn][c] = 0.f;
                int col = hn * 64 + jn * 8 + g;
                uint32_t bf[2];
                bf[0] = *(const uint32_t*)(Ks + col * LDQH + 2 * tq);
                bf[1] = *(const uint32_t*)(Ks + col * LDQH + 8 + 2 * tq);
                mma_f16(s[jn], af, bf);
            }
#pragma unroll
            for (int jn = 0; jn < 8; jn++) {
                int c0 = hn * 64 + jn * 8 + 2 * tq;
                int gc0 = jt * 128 + c0;
#pragma unroll
                for (int rr = 0; rr < 2; rr++) {
                    int rl = row0 + rr * 8;
                    int grow = qt * 128 + rl;
                    float p0 = fast_exp(s[jn][rr * 2 + 0]);
                    float p1 = fast_exp(s[jn][rr * 2 + 1]);
                    if (gc0 == grow)     p0 = 0.f;
                    if (gc0 + 1 == grow) p1 = 0.f;
                    lsum[rr] += p0 + p1;
                    *(__half2*)(Ps + rl * LDPH + c0) = __floats2half2_rn(p0, p1);
                }
            }
        }
        __syncthreads();

        // O += P @ V
#pragma unroll
        for (int ksi = 0; ksi < 8; ksi++) {
            uint32_t pa[4];
            pa[0] = *(const uint32_t*)(Ps + row0 * LDPH + ksi * 16 + 2 * tq);
            pa[1] = *(const uint32_t*)(Ps + (row0 + 8) * LDPH + ksi * 16 + 2 * tq);
            pa[2] = *(const uint32_t*)(Ps + row0 * LDPH + ksi * 16 + 8 + 2 * tq);
            pa[3] = *(const uint32_t*)(Ps + (row0 + 8) * LDPH + ksi * 16 + 8 + 2 * tq);
#pragma unroll
            for (int jn = 0; jn < 2; jn++) {
                int col = jn * 8 + g;
                uint32_t bf[2];
                bf[0] = *(const uint32_t*)(Vs + col * LDPH + ksi * 16 + 2 * tq);
                bf[1] = *(const uint32_t*)(Vs + col * LDPH + ksi * 16 + 8 + 2 * tq);
                mma_f16(o[jn], pa, bf);
            }
        }
        __syncthreads();
    }

#pragma unroll
    for (int rr = 0; rr < 2; rr++) {
        lsum[rr] += __shfl_xor_sync(0xFFFFFFFF, lsum[rr], 1);
        lsum[rr] += __shfl_xor_sync(0xFFFFFFFF, lsum[rr], 2);
    }
    float inv[2] = {1.f / lsum[0], 1.f / lsum[1]};

#pragma unroll
    for (int rr = 0; rr < 2; rr++) {
        int tok = seq0 + qt * 128 + row0 + rr * 8;
        __half* dst = g_h1 + (size_t)tok * H1LD + r * DIN1 + hh * HD;
#pragma unroll
        for (int jn = 0; jn < 2; jn++) {
            int col = jn * 8 + 2 * tq;
            *(__half2*)(dst + col) = __floats2half2_rn(o[jn][rr * 2 + 0] * inv[rr],
                                                       o[jn][rr * 2 + 1] * inv[rr]);
        }
    }
}

// ============================================================
extern "C" void kernel_launch(void* const* d_in, const int* in_sizes, int n_in,
                              void* d_out, int out_size)
{
    const float* x    = (const float*)d_in[0];
    const float* rs   = (const float*)d_in[1];
    const float* Wq   = (const float*)d_in[2];
    const float* bq   = (const float*)d_in[3];
    const float* Wk   = (const float*)d_in[4];
    const float* bk   = (const float*)d_in[5];
    const float* Wv   = (const float*)d_in[6];
    const float* bv   = (const float*)d_in[7];
    const float* Win  = (const float*)d_in[8];
    const float* b_in = (const float*)d_in[9];
    const float* W1   = (const float*)d_in[10];
    const float* b1   = (const float*)d_in[11];
    const float* W2   = (const float*)d_in[12];
    const float* b2   = (const float*)d_in[13];
    float* out = (float*)d_out;

    cudaFuncSetAttribute(mma_gemm<0>, cudaFuncAttributeMaxDynamicSharedMemorySize, GEMM_SMEM);
    cudaFuncSetAttribute(mma_gemm<2>, cudaFuncAttributeMaxDynamicSharedMemorySize, GEMM_SMEM);
    cudaFuncSetAttribute(mma_gemm<3>, cudaFuncAttributeMaxDynamicSharedMemorySize, GEMM_SMEM);
    cudaFuncSetAttribute(fa_kernel, cudaFuncAttributeMaxDynamicSharedMemorySize, FA_SMEM);

    conv_all<<<2132, 256>>>(x, Wq, Wk, Wv, Win, W1, W2);

    mma_gemm<0><<<dim3(4, 32, 4), 256, GEMM_SMEM>>>(bq, bk, bv, b_in, b1, b2, rs, out);
    fa_kernel<<<dim3(4, GQ, 8), 256, FA_SMEM>>>();
    mma_gemm<2><<<dim3(4, 32, 4), 256, GEMM_SMEM>>>(bq, bk, bv, b_in, b1, b2, rs, out);
    mma_gemm<3><<<dim3(4, 32, 1), 256, GEMM_SMEM>>>(bq, bk, bv, b_in, b1, b2, rs, out);
}

// round 9
// speedup vs baseline: 1.8820x; 1.0791x over previous
#include <cuda_runtime.h>
#include <cuda_fp16.h>
#include <cstdint>

#define TOK   4096
#define DIMN  512
#define GQ    32
#define HD    16
#define RNUM  4
#define INTER 405
#define INTP  408
#define DIN1  144
#define H1LD  576
#define HSLDP 1632
#define NSEQ  512

// ---------------- device scratch (fp16 payloads) ----------------
__device__ __half g_xc[TOK * DIMN];
__device__ __half g_wqt[DIMN * DIMN];     // [n][k]
__device__ __half g_wkt[DIMN * DIMN];
__device__ __half g_wvt[DIMN * DIMN];
__device__ __half g_wint[64 * DIMN];
__device__ __half g_w1t[RNUM * INTP * DIN1];   // per rule [408][144], pad rows zero
__device__ __half g_w2t[DIMN * HSLDP];         // [512][1632], pad k zero
__device__ __half g_qkv[3 * TOK * DIMN];
__device__ __half g_h1[TOK * H1LD];
__device__ __half g_hs[TOK * HSLDP];           // per rule stride 408, pads stay zero

// ---------------- helpers ----------------
__device__ __forceinline__ uint32_t smem_u32(const void* p) {
    uint32_t a;
    asm("{ .reg .u64 t; cvta.to.shared.u64 t, %1; cvt.u32.u64 %0, t; }"
        : "=r"(a) : "l"(p));
    return a;
}
__device__ __forceinline__ void cp16(uint32_t dst, const void* src, bool pred) {
    int sz = pred ? 16 : 0;
    asm volatile("cp.async.ca.shared.global [%0], [%1], 16, %2;"
                 :: "r"(dst), "l"(src), "r"(sz) : "memory");
}
#define CP_COMMIT() asm volatile("cp.async.commit_group;" ::: "memory")
#define CP_WAIT1()  asm volatile("cp.async.wait_group 1;" ::: "memory")
#define CP_WAIT0()  asm volatile("cp.async.wait_group 0;" ::: "memory")

__device__ __forceinline__ void mma_f16(float d[4], const uint32_t a[4],
                                        const uint32_t b[2]) {
    asm volatile(
        "mma.sync.aligned.m16n8k16.row.col.f32.f16.f16.f32 "
        "{%0,%1,%2,%3}, {%4,%5,%6,%7}, {%8,%9}, {%0,%1,%2,%3};"
        : "+f"(d[0]), "+f"(d[1]), "+f"(d[2]), "+f"(d[3])
        : "r"(a[0]), "r"(a[1]), "r"(a[2]), "r"(a[3]), "r"(b[0]), "r"(b[1]));
}

// FFMA-pipe exp
__device__ __forceinline__ float fast_exp(float s) {
    s = fminf(fmaxf(s, -80.0f), 80.0f);
    float n = rintf(s * 1.4426950408889634f);
    float f = fmaf(n, -0.6931471805599453f, s);
    float p = 1.3888888889e-3f;
    p = fmaf(p, f, 8.3333333333e-3f);
    p = fmaf(p, f, 4.1666666667e-2f);
    p = fmaf(p, f, 1.6666666667e-1f);
    p = fmaf(p, f, 0.5f);
    p = fmaf(p, f, 1.0f);
    p = fmaf(p, f, 1.0f);
    int e = (int)n;
    return p * __int_as_float((e + 127) << 23);
}

// ---------------- one-shot conversion + weight transposes ----------------
__device__ void trans_tile(const float* __restrict__ src, __half* __restrict__ dst,
                           int K, int N, int ldk, int tk, int tn, bool w2remap)
{
    __shared__ float tl[32][33];
    int tx = threadIdx.x & 31, ty = threadIdx.x >> 5;   // 32 x 8
    int k0 = tk * 32, n0 = tn * 32;
#pragma unroll
    for (int i = 0; i < 4; i++) {
        int k = k0 + ty + i * 8, n = n0 + tx;
        tl[ty + i * 8][tx] = (k < K && n < N) ? src[(size_t)k * N + n] : 0.f;
    }
    __syncthreads();
#pragma unroll
    for (int i = 0; i < 4; i++) {
        int n = n0 + ty + i * 8, k = k0 + tx;
        if (n < N && k < K) {
            int kk = w2remap ? k + 3 * (k / 405) : k;
            dst[(size_t)n * ldk + kk] = __float2half_rn(tl[tx][ty + i * 8]);
        }
    }
}

__global__ void conv_all(const float* __restrict__ x,  const float* __restrict__ Wq,
                         const float* __restrict__ Wk, const float* __restrict__ Wv,
                         const float* __restrict__ Win, const float* __restrict__ W1,
                         const float* __restrict__ W2)
{
    int b = blockIdx.x;
    if (b < 256) {
#pragma unroll
        for (int u = 0; u < 32; u++) {
            int i = b * 8192 + u * 256 + threadIdx.x;
            g_xc[i] = __float2half_rn(x[i]);
        }
    } else if (b < 512) {
        int i = b - 256;  trans_tile(Wq, g_wqt, 512, 512, 512, i / 16, i % 16, false);
    } else if (b < 768) {
        int i = b - 512;  trans_tile(Wk, g_wkt, 512, 512, 512, i / 16, i % 16, false);
    } else if (b < 1024) {
        int i = b - 768;  trans_tile(Wv, g_wvt, 512, 512, 512, i / 16, i % 16, false);
    } else if (b < 1056) {
        int i = b - 1024; trans_tile(Win, g_wint, 512, 64, 512, i / 2, i % 2, false);
    } else if (b < 1316) {
        int i = b - 1056; int r = i / 65, rem = i % 65;
        trans_tile(W1 + (size_t)r * DIN1 * INTER, g_w1t + (size_t)r * INTP * DIN1,
                   DIN1, INTER, DIN1, rem / 13, rem % 13, false);
    } else {
        int i = b - 1316;
        trans_tile(W2, g_w2t, 1620, 512, HSLDP, i / 16, i % 16, true);
    }
}

// ============================================================
// fp16 mma GEMM, CTA 128x128, KC=64, 8 warps, warp tile 32x64,
// 2-stage cp.async (compute -> barrier -> issue t+2 -> wait -> barrier).
//   MODE 0: z=0..2 q/k/v; z=3 in_proj (N=64, bx==0)
//   MODE 2: MLP1 per rule z (K=144 -> KT=3)
//   MODE 3: MLP2 (K=1632 padded -> KT=26, +sum_r rs*b2 -> out) + rs tail
// ============================================================
#define KC     64
#define LDH    72                  /* halves per smem row (64 + 8 pad) */
#define ABUFH  (128 * LDH)
#define BBUFH  (128 * LDH)
#define BUFH   (ABUFH + BBUFH)
#define GEMM_SMEM (2 * BUFH * 2)   /* 73728 bytes */

template<int MODE>
__global__ void __launch_bounds__(256, 2) mma_gemm(
    const float* __restrict__ bq, const float* __restrict__ bk,
    const float* __restrict__ bv, const float* __restrict__ b_in,
    const float* __restrict__ b1, const float* __restrict__ b2,
    const float* __restrict__ rs, float* __restrict__ out)
{
    extern __shared__ __half dynsh[];
    const uint32_t smbase = smem_u32(dynsh);

    const int tid = threadIdx.x;
    const int wid = tid >> 5, lane = tid & 31;
    const int wm = wid >> 1, wn = wid & 1;
    const int g = lane >> 2, tq = lane & 3;
    const int m_base = blockIdx.y * 128;
    const int n_base = blockIdx.x * 128;
    const int z = blockIdx.z;

    const __half* A; const __half* Bt; const float* bias;
    int lda, K, Nrows, ldbk;
    if (MODE == 0) {
        A = g_xc + (size_t)m_base * DIMN; lda = DIMN; K = DIMN;
        if (z == 3) {
            if (blockIdx.x != 0) return;
            Bt = g_wint; Nrows = 64; ldbk = DIMN; bias = b_in;
        } else {
            Bt = (z == 0) ? g_wqt : (z == 1) ? g_wkt : g_wvt;
            Nrows = 512; ldbk = DIMN;
            bias = (z == 0) ? bq : (z == 1) ? bk : bv;
        }
    }
    if (MODE == 2) {
        A = g_h1 + (size_t)m_base * H1LD + z * DIN1; lda = H1LD; K = DIN1;
        Bt = g_w1t + (size_t)z * INTP * DIN1; Nrows = INTP; ldbk = DIN1;
        bias = b1 + z * INTER;
    }
    if (MODE == 3) {
        A = g_hs + (size_t)m_base * HSLDP; lda = HSLDP; K = HSLDP;
        Bt = g_w2t; Nrows = 512; ldbk = HSLDP; bias = b2;
    }

    float d[2][8][4];
#pragma unroll
    for (int i = 0; i < 2; i++)
#pragma unroll
        for (int j = 0; j < 8; j++)
#pragma unroll
            for (int c = 0; c < 4; c++) d[i][j][c] = 0.f;

    const int KT = (K + KC - 1) / KC;   // >= 3 for all modes

    // loader: per matrix 128 rows x 8 groups(8 halves) = 1024 chunks / 256 thr = 4 each
#define ISSUE(k0, buf)                                                         \
    do {                                                                       \
        uint32_t sA = smbase + (uint32_t)((buf) * BUFH) * 2u;                  \
        uint32_t sB = sA + (uint32_t)ABUFH * 2u;                               \
        _Pragma("unroll")                                                      \
        for (int i = 0; i < 4; i++) {                                          \
            int idx = tid + (i << 8);                                          \
            int row = idx >> 3, grp = idx & 7;                                 \
            int kk = (k0) + grp * 8;                                           \
            bool pk = kk < K;                                                  \
            int kcl = pk ? kk : 0;                                             \
            cp16(sA + (uint32_t)(row * LDH + grp * 8) * 2u,                    \
                 A + (size_t)row * lda + kcl, pk);                             \
            bool pb = pk && (n_base + row) < Nrows;                            \
            int brow = ((n_base + row) < Nrows) ? (n_base + row) : 0;          \
            cp16(sB + (uint32_t)(row * LDH + grp * 8) * 2u,                    \
                 Bt + (size_t)brow * ldbk + kcl, pb);                          \
        }                                                                      \
    } while (0)

    ISSUE(0, 0);
    CP_COMMIT();
    ISSUE(KC, 1);
    CP_COMMIT();
    CP_WAIT1();
    __syncthreads();

    for (int t = 0; t < KT; t++) {
        const __half* As_ = dynsh + (t & 1) * BUFH;
        const __half* Bs_ = As_ + ABUFH;
#pragma unroll
        for (int ks = 0; ks < 4; ks++) {
            uint32_t bf[8][2];
#pragma unroll
            for (int j = 0; j < 8; j++) {
                int col = wn * 64 + j * 8 + g;
                bf[j][0] = *(const uint32_t*)(Bs_ + col * LDH + ks * 16 + 2 * tq);
                bf[j][1] = *(const uint32_t*)(Bs_ + col * LDH + ks * 16 + 8 + 2 * tq);
            }
#pragma unroll
            for (int i = 0; i < 2; i++) {
                int r0 = wm * 32 + i * 16 + g;
                uint32_t af[4];
                af[0] = *(const uint32_t*)(As_ + r0 * LDH + ks * 16 + 2 * tq);
                af[1] = *(const uint32_t*)(As_ + (r0 + 8) * LDH + ks * 16 + 2 * tq);
                af[2] = *(const uint32_t*)(As_ + r0 * LDH + ks * 16 + 8 + 2 * tq);
                af[3] = *(const uint32_t*)(As_ + (r0 + 8) * LDH + ks * 16 + 8 + 2 * tq);
#pragma unroll
                for (int j = 0; j < 8; j++)
                    mma_f16(d[i][j], af, bf[j]);
            }
        }
        __syncthreads();                       // all warps done reading buf t&1
        if (t + 2 < KT) { ISSUE((t + 2) * KC, t & 1); CP_COMMIT(); }
        if (t + 1 < KT) {
            if (t + 2 < KT) CP_WAIT1(); else CP_WAIT0();
            __syncthreads();                   // buf (t+1)&1 data visible
        }
    }

    // ---------------- epilogue ----------------
#pragma unroll
    for (int i = 0; i < 2; i++) {
        int mr[2];
        mr[0] = m_base + wm * 32 + i * 16 + g;
        mr[1] = mr[0] + 8;
#pragma unroll
        for (int j = 0; j < 8; j++) {
            int n0 = n_base + wn * 64 + j * 8 + tq * 2;
#pragma unroll
            for (int rr = 0; rr < 2; rr++) {
                float v0 = d[i][j][rr * 2 + 0];
                float v1 = d[i][j][rr * 2 + 1];
                int m = mr[rr];
                if (MODE == 0) {
                    if (z == 3) {
                        if (n0 < 64) {
                            int r0i = n0 >> 4, d0i = n0 & 15;
                            int r1i = (n0 + 1) >> 4, d1i = (n0 + 1) & 15;
                            g_h1[(size_t)m * H1LD + r0i * DIN1 + 128 + d0i] =
                                __float2half_rn(v0 + b_in[n0]);
                            g_h1[(size_t)m * H1LD + r1i * DIN1 + 128 + d1i] =
                                __float2half_rn(v1 + b_in[n0 + 1]);
                        }
                    } else {
                        __half* C = g_qkv + (size_t)z * TOK * DIMN;
                        *(__half2*)(C + (size_t)m * DIMN + n0) =
                            __floats2half2_rn(v0 + bias[n0], v1 + bias[n0 + 1]);
                    }
                } else if (MODE == 2) {
                    float rsv = rs[m * RNUM + z];
                    size_t base = (size_t)m * HSLDP + z * INTP + n0;
                    if (n0 + 1 < INTER) {
                        *(__half2*)(g_hs + base) = __floats2half2_rn(
                            fmaxf(v0 + bias[n0], 0.f) * rsv,
                            fmaxf(v1 + bias[n0 + 1], 0.f) * rsv);
                    } else if (n0 < INTER) {
                        g_hs[base] = __float2half_rn(fmaxf(v0 + bias[n0], 0.f) * rsv);
                    }
                } else {
                    float4 q = *(const float4*)(rs + m * RNUM);
                    float b0 = q.x * bias[n0]            + q.y * bias[DIMN + n0]
                             + q.z * bias[2 * DIMN + n0] + q.w * bias[3 * DIMN + n0];
                    float b1v = q.x * bias[n0 + 1]            + q.y * bias[DIMN + n0 + 1]
                              + q.z * bias[2 * DIMN + n0 + 1] + q.w * bias[3 * DIMN + n0 + 1];
                    *(float2*)(out + (size_t)m * DIMN + n0) =
                        make_float2(v0 + b0, v1 + b1v);
                }
            }
        }
    }

    if (MODE == 3 && blockIdx.x == 0) {
        int idx = blockIdx.y * 512 + tid * 2;
        *(float2*)(out + (size_t)TOK * DIMN + idx) = *(const float2*)(rs + idx);
    }
#undef ISSUE
}

// ============================================================
// Flash attention, fp16 mma (unchanged from R8).
// ============================================================
#define LDQH 24
#define LDPH 136
#define FA_SMEM ((128 * LDQH * 2 + 16 * LDPH + 128 * LDPH) * 2)

__global__ void __launch_bounds__(256, 2) fa_kernel()
{
    extern __shared__ __half fsh[];
    __half* Qs = fsh;
    __half* Ks = fsh + 128 * LDQH;
    __half* Vs = fsh + 2 * 128 * LDQH;
    __half* Ps = Vs + 16 * LDPH;

    const int qt = blockIdx.x;
    const int gg = blockIdx.y;
    const int bb = blockIdx.z;
    const int r = gg >> 3, hh = gg & 7;
    const int tid = threadIdx.x;
    const int wid = tid >> 5, lane = tid & 31;
    const int g = lane >> 2, tq = lane & 3;

    const __half* gq = g_qkv;
    const __half* gk = g_qkv + (size_t)TOK * DIMN;
    const __half* gv = g_qkv + 2 * (size_t)TOK * DIMN;
    const int seq0 = bb * NSEQ;

    const __half2 qscale = __floats2half2_rn(0.25f, 0.25f);

    {
        int row = tid >> 1, part = tid & 1;
        int tok = seq0 + qt * 128 + row;
        uint4 v = *(const uint4*)(gq + (size_t)tok * DIMN + gg * HD + part * 8);
        __half2* pv = (__half2*)&v;
#pragma unroll
        for (int l = 0; l < 4; l++) pv[l] = __hmul2(pv[l], qscale);
        *(uint4*)(Qs + row * LDQH + part * 8) = v;
    }

    float o[2][4];
#pragma unroll
    for (int j = 0; j < 2; j++)
#pragma unroll
        for (int c = 0; c < 4; c++) o[j][c] = 0.f;
    float lsum[2] = {0.f, 0.f};

    const int row0 = wid * 16 + g;

    for (int jt = 0; jt < 4; jt++) {
        {
            int row = tid >> 1, part = tid & 1;
            int tok = seq0 + jt * 128 + row;
            uint4 kv = *(const uint4*)(gk + (size_t)tok * DIMN + gg * HD + part * 8);
            *(uint4*)(Ks + row * LDQH + part * 8) = kv;
            uint4 vv = *(const uint4*)(gv + (size_t)tok * DIMN + gg * HD + part * 8);
            __half tmp[8];
            *(uint4*)tmp = vv;
            int d0 = part * 8;
#pragma unroll
            for (int l = 0; l < 8; l++) Vs[(d0 + l) * LDPH + row] = tmp[l];
        }
        __syncthreads();

        uint32_t af[4];
        af[0] = *(const uint32_t*)(Qs + row0 * LDQH + 2 * tq);
        af[1] = *(const uint32_t*)(Qs + (row0 + 8) * LDQH + 2 * tq);
        af[2] = *(const uint32_t*)(Qs + row0 * LDQH + 8 + 2 * tq);
        af[3] = *(const uint32_t*)(Qs + (row0 + 8) * LDQH + 8 + 2 * tq);

#pragma unroll
        for (int hn = 0; hn < 2; hn++) {
            float s[8][4];
#pragma unroll
            for (int jn = 0; jn < 8; jn++) {
#pragma unroll
                for (int c = 0; c < 4; c++) s[jn][c] = 0.f;
                int col = hn * 64 + jn * 8 + g;
                uint32_t bf[2];
                bf[0] = *(const uint32_t*)(Ks + col * LDQH + 2 * tq);
                bf[1] = *(const uint32_t*)(Ks + col * LDQH + 8 + 2 * tq);
                mma_f16(s[jn], af, bf);
            }
#pragma unroll
            for (int jn = 0; jn < 8; jn++) {
                int c0 = hn * 64 + jn * 8 + 2 * tq;
                int gc0 = jt * 128 + c0;
#pragma unroll
                for (int rr = 0; rr < 2; rr++) {
                    int rl = row0 + rr * 8;
                    int grow = qt * 128 + rl;
                    float p0 = fast_exp(s[jn][rr * 2 + 0]);
                    float p1 = fast_exp(s[jn][rr * 2 + 1]);
                    if (gc0 == grow)     p0 = 0.f;
                    if (gc0 + 1 == grow) p1 = 0.f;
                    lsum[rr] += p0 + p1;
                    *(__half2*)(Ps + rl * LDPH + c0) = __floats2half2_rn(p0, p1);
                }
            }
        }
        __syncthreads();

#pragma unroll
        for (int ksi = 0; ksi < 8; ksi++) {
            uint32_t pa[4];
            pa[0] = *(const uint32_t*)(Ps + row0 * LDPH + ksi * 16 + 2 * tq);
            pa[1] = *(const uint32_t*)(Ps + (row0 + 8) * LDPH + ksi * 16 + 2 * tq);
            pa[2] = *(const uint32_t*)(Ps + row0 * LDPH + ksi * 16 + 8 + 2 * tq);
            pa[3] = *(const uint32_t*)(Ps + (row0 + 8) * LDPH + ksi * 16 + 8 + 2 * tq);
#pragma unroll
            for (int jn = 0; jn < 2; jn++) {
                int col = jn * 8 + g;
                uint32_t bf[2];
                bf[0] = *(const uint32_t*)(Vs + col * LDPH + ksi * 16 + 2 * tq);
                bf[1] = *(const uint32_t*)(Vs + col * LDPH + ksi * 16 + 8 + 2 * tq);
                mma_f16(o[jn], pa, bf);
            }
        }
        __syncthreads();
    }

#pragma unroll
    for (int rr = 0; rr < 2; rr++) {
        lsum[rr] += __shfl_xor_sync(0xFFFFFFFF, lsum[rr], 1);
        lsum[rr] += __shfl_xor_sync(0xFFFFFFFF, lsum[rr], 2);
    }
    float inv[2] = {1.f / lsum[0], 1.f / lsum[1]};

#pragma unroll
    for (int rr = 0; rr < 2; rr++) {
        int tok = seq0 + qt * 128 + row0 + rr * 8;
        __half* dst = g_h1 + (size_t)tok * H1LD + r * DIN1 + hh * HD;
#pragma unroll
        for (int jn = 0; jn < 2; jn++) {
            int col = jn * 8 + 2 * tq;
            *(__half2*)(dst + col) = __floats2half2_rn(o[jn][rr * 2 + 0] * inv[rr],
                                                       o[jn][rr * 2 + 1] * inv[rr]);
        }
    }
}

// ============================================================
extern "C" void kernel_launch(void* const* d_in, const int* in_sizes, int n_in,
                              void* d_out, int out_size)
{
    const float* x    = (const float*)d_in[0];
    const float* rs   = (const float*)d_in[1];
    const float* Wq   = (const float*)d_in[2];
    const float* bq   = (const float*)d_in[3];
    const float* Wk   = (const float*)d_in[4];
    const float* bk   = (const float*)d_in[5];
    const float* Wv   = (const float*)d_in[6];
    const float* bv   = (const float*)d_in[7];
    const float* Win  = (const float*)d_in[8];
    const float* b_in = (const float*)d_in[9];
    const float* W1   = (const float*)d_in[10];
    const float* b1   = (const float*)d_in[11];
    const float* W2   = (const float*)d_in[12];
    const float* b2   = (const float*)d_in[13];
    float* out = (float*)d_out;

    cudaFuncSetAttribute(mma_gemm<0>, cudaFuncAttributeMaxDynamicSharedMemorySize, GEMM_SMEM);
    cudaFuncSetAttribute(mma_gemm<2>, cudaFuncAttributeMaxDynamicSharedMemorySize, GEMM_SMEM);
    cudaFuncSetAttribute(mma_gemm<3>, cudaFuncAttributeMaxDynamicSharedMemorySize, GEMM_SMEM);
    cudaFuncSetAttribute(fa_kernel, cudaFuncAttributeMaxDynamicSharedMemorySize, FA_SMEM);

    conv_all<<<2132, 256>>>(x, Wq, Wk, Wv, Win, W1, W2);

    mma_gemm<0><<<dim3(4, 32, 4), 256, GEMM_SMEM>>>(bq, bk, bv, b_in, b1, b2, rs, out);
    fa_kernel<<<dim3(4, GQ, 8), 256, FA_SMEM>>>();
    mma_gemm<2><<<dim3(4, 32, 4), 256, GEMM_SMEM>>>(bq, bk, bv, b_in, b1, b2, rs, out);
    mma_gemm<3><<<dim3(4, 32, 1), 256, GEMM_SMEM>>>(bq, bk, bv, b_in, b1, b2, rs, out);
}

// round 10
// speedup vs baseline: 1.9624x; 1.0427x over previous
#include <cuda_runtime.h>
#include <cuda_fp16.h>
#include <cstdint>

#define TOK   4096
#define DIMN  512
#define GQ    32
#define HD    16
#define RNUM  4
#define INTER 405
#define INTP  408
#define DIN1  144
#define H1LD  576
#define HSLDP 1632
#define NSEQ  512

// ---------------- device scratch (fp16 payloads) ----------------
__device__ __half g_xc[TOK * DIMN];
__device__ __half g_wqt[DIMN * DIMN];     // [n][k]
__device__ __half g_wkt[DIMN * DIMN];
__device__ __half g_wvt[DIMN * DIMN];
__device__ __half g_wint[64 * DIMN];
__device__ __half g_w1t[RNUM * INTP * DIN1];   // per rule [408][144]
__device__ __half g_w2t[DIMN * HSLDP];         // [512][1632], pad k zero
__device__ __half g_qkv[3 * TOK * DIMN];
__device__ __half g_h1[TOK * H1LD];
__device__ __half g_hs[TOK * HSLDP];

// ---------------- helpers ----------------
__device__ __forceinline__ uint32_t smem_u32(const void* p) {
    uint32_t a;
    asm("{ .reg .u64 t; cvta.to.shared.u64 t, %1; cvt.u32.u64 %0, t; }"
        : "=r"(a) : "l"(p));
    return a;
}
__device__ __forceinline__ void cp16(uint32_t dst, const void* src, bool pred) {
    int sz = pred ? 16 : 0;
    asm volatile("cp.async.ca.shared.global [%0], [%1], 16, %2;"
                 :: "r"(dst), "l"(src), "r"(sz) : "memory");
}
#define CP_COMMIT() asm volatile("cp.async.commit_group;" ::: "memory")
#define CP_WAIT1()  asm volatile("cp.async.wait_group 1;" ::: "memory")
#define CP_WAIT0()  asm volatile("cp.async.wait_group 0;" ::: "memory")

__device__ __forceinline__ void mma_f16(float d[4], const uint32_t a[4],
                                        const uint32_t b[2]) {
    asm volatile(
        "mma.sync.aligned.m16n8k16.row.col.f32.f16.f16.f32 "
        "{%0,%1,%2,%3}, {%4,%5,%6,%7}, {%8,%9}, {%0,%1,%2,%3};"
        : "+f"(d[0]), "+f"(d[1]), "+f"(d[2]), "+f"(d[3])
        : "r"(a[0]), "r"(a[1]), "r"(a[2]), "r"(a[3]), "r"(b[0]), "r"(b[1]));
}
__device__ __forceinline__ void ldsm_x4(uint32_t& r0, uint32_t& r1,
                                        uint32_t& r2, uint32_t& r3, uint32_t addr) {
    asm volatile("ldmatrix.sync.aligned.m8n8.x4.shared.b16 {%0,%1,%2,%3}, [%4];"
                 : "=r"(r0), "=r"(r1), "=r"(r2), "=r"(r3) : "r"(addr));
}

// FFMA-pipe exp
__device__ __forceinline__ float fast_exp(float s) {
    s = fminf(fmaxf(s, -80.0f), 80.0f);
    float n = rintf(s * 1.4426950408889634f);
    float f = fmaf(n, -0.6931471805599453f, s);
    float p = 1.3888888889e-3f;
    p = fmaf(p, f, 8.3333333333e-3f);
    p = fmaf(p, f, 4.1666666667e-2f);
    p = fmaf(p, f, 1.6666666667e-1f);
    p = fmaf(p, f, 0.5f);
    p = fmaf(p, f, 1.0f);
    p = fmaf(p, f, 1.0f);
    int e = (int)n;
    return p * __int_as_float((e + 127) << 23);
}

// ---------------- one-shot conversion + weight transposes ----------------
__device__ void trans_tile(const float* __restrict__ src, __half* __restrict__ dst,
                           int K, int N, int ldk, int tk, int tn, bool w2remap)
{
    __shared__ float tl[32][33];
    int tx = threadIdx.x & 31, ty = threadIdx.x >> 5;
    int k0 = tk * 32, n0 = tn * 32;
#pragma unroll
    for (int i = 0; i < 4; i++) {
        int k = k0 + ty + i * 8, n = n0 + tx;
        tl[ty + i * 8][tx] = (k < K && n < N) ? src[(size_t)k * N + n] : 0.f;
    }
    __syncthreads();
#pragma unroll
    for (int i = 0; i < 4; i++) {
        int n = n0 + ty + i * 8, k = k0 + tx;
        if (n < N && k < K) {
            int kk = w2remap ? k + 3 * (k / 405) : k;
            dst[(size_t)n * ldk + kk] = __float2half_rn(tl[tx][ty + i * 8]);
        }
    }
}

__global__ void conv_all(const float* __restrict__ x,  const float* __restrict__ Wq,
                         const float* __restrict__ Wk, const float* __restrict__ Wv,
                         const float* __restrict__ Win, const float* __restrict__ W1,
                         const float* __restrict__ W2)
{
    int b = blockIdx.x;
    if (b < 256) {
#pragma unroll
        for (int u = 0; u < 32; u++) {
            int i = b * 8192 + u * 256 + threadIdx.x;
            g_xc[i] = __float2half_rn(x[i]);
        }
    } else if (b < 512) {
        int i = b - 256;  trans_tile(Wq, g_wqt, 512, 512, 512, i / 16, i % 16, false);
    } else if (b < 768) {
        int i = b - 512;  trans_tile(Wk, g_wkt, 512, 512, 512, i / 16, i % 16, false);
    } else if (b < 1024) {
        int i = b - 768;  trans_tile(Wv, g_wvt, 512, 512, 512, i / 16, i % 16, false);
    } else if (b < 1056) {
        int i = b - 1024; trans_tile(Win, g_wint, 512, 64, 512, i / 2, i % 2, false);
    } else if (b < 1316) {
        int i = b - 1056; int r = i / 65, rem = i % 65;
        trans_tile(W1 + (size_t)r * DIN1 * INTER, g_w1t + (size_t)r * INTP * DIN1,
                   DIN1, INTER, DIN1, rem / 13, rem % 13, false);
    } else {
        int i = b - 1316;
        trans_tile(W2, g_w2t, 1620, 512, HSLDP, i / 16, i % 16, true);
    }
}

// ============================================================
// fp16 mma GEMM, CTA 128x128, KC=64, 8 warps, warp tile 32x64,
// 2-stage cp.async + ldmatrix.x4 fragment loads.
// ============================================================
#define KC     64
#define LDH    72
#define ABUFH  (128 * LDH)
#define BBUFH  (128 * LDH)
#define BUFH   (ABUFH + BBUFH)
#define GEMM_SMEM (2 * BUFH * 2)

template<int MODE>
__global__ void __launch_bounds__(256, 2) mma_gemm(
    const float* __restrict__ bq, const float* __restrict__ bk,
    const float* __restrict__ bv, const float* __restrict__ b_in,
    const float* __restrict__ b1, const float* __restrict__ b2,
    const float* __restrict__ rs, float* __restrict__ out)
{
    extern __shared__ __half dynsh[];
    const uint32_t smbase = smem_u32(dynsh);

    const int tid = threadIdx.x;
    const int wid = tid >> 5, lane = tid & 31;
    const int wm = wid >> 1, wn = wid & 1;
    const int g = lane >> 2, tq = lane & 3;
    const int m_base = blockIdx.y * 128;
    const int n_base = blockIdx.x * 128;
    const int z = blockIdx.z;

    const __half* A; const __half* Bt; const float* bias;
    int lda, K, Nrows, ldbk;
    if (MODE == 0) {
        A = g_xc + (size_t)m_base * DIMN; lda = DIMN; K = DIMN;
        if (z == 3) {
            if (blockIdx.x != 0) return;
            Bt = g_wint; Nrows = 64; ldbk = DIMN; bias = b_in;
        } else {
            Bt = (z == 0) ? g_wqt : (z == 1) ? g_wkt : g_wvt;
            Nrows = 512; ldbk = DIMN;
            bias = (z == 0) ? bq : (z == 1) ? bk : bv;
        }
    }
    if (MODE == 2) {
        A = g_h1 + (size_t)m_base * H1LD + z * DIN1; lda = H1LD; K = DIN1;
        Bt = g_w1t + (size_t)z * INTP * DIN1; Nrows = INTP; ldbk = DIN1;
        bias = b1 + z * INTER;
    }
    if (MODE == 3) {
        A = g_hs + (size_t)m_base * HSLDP; lda = HSLDP; K = HSLDP;
        Bt = g_w2t; Nrows = 512; ldbk = HSLDP; bias = b2;
    }

    float d[2][8][4];
#pragma unroll
    for (int i = 0; i < 2; i++)
#pragma unroll
        for (int j = 0; j < 8; j++)
#pragma unroll
            for (int c = 0; c < 4; c++) d[i][j][c] = 0.f;

    const int KT = (K + KC - 1) / KC;

    // ldmatrix lane addressing: l8 = lane%8 (row within 8x8), lm = lane/8 (matrix idx)
    const int l8 = lane & 7, lm = lane >> 3;
    // A x4 tiles: m0=(r,k0) m1=(r+8,k0) m2=(r,k8) m3=(r+8,k8)
    const uint32_t offA0 = (uint32_t)(((wm * 32 + (lm & 1) * 8 + l8) * LDH
                                       + (lm >> 1) * 8) * 2);
    const uint32_t offA1 = offA0 + (uint32_t)(16 * LDH * 2);
    // B x4 tiles: m0=(n j,k0) m1=(n j,k8) m2=(n j+1,k0) m3=(n j+1,k8)
    uint32_t offB[4];
#pragma unroll
    for (int jj = 0; jj < 4; jj++)
        offB[jj] = (uint32_t)(((wn * 64 + jj * 16 + (lm >> 1) * 8 + l8) * LDH
                               + (lm & 1) * 8) * 2);

#define ISSUE(k0, buf)                                                         \
    do {                                                                       \
        uint32_t sA = smbase + (uint32_t)((buf) * BUFH) * 2u;                  \
        uint32_t sB = sA + (uint32_t)ABUFH * 2u;                               \
        _Pragma("unroll")                                                      \
        for (int i = 0; i < 4; i++) {                                          \
            int idx = tid + (i << 8);                                          \
            int row = idx >> 3, grp = idx & 7;                                 \
            int kk = (k0) + grp * 8;                                           \
            bool pk = kk < K;                                                  \
            int kcl = pk ? kk : 0;                                             \
            cp16(sA + (uint32_t)(row * LDH + grp * 8) * 2u,                    \
                 A + (size_t)row * lda + kcl, pk);                             \
            bool pb = pk && (n_base + row) < Nrows;                            \
            int brow = ((n_base + row) < Nrows) ? (n_base + row) : 0;          \
            cp16(sB + (uint32_t)(row * LDH + grp * 8) * 2u,                    \
                 Bt + (size_t)brow * ldbk + kcl, pb);                          \
        }                                                                      \
    } while (0)

    ISSUE(0, 0);
    CP_COMMIT();
    ISSUE(KC, 1);
    CP_COMMIT();
    CP_WAIT1();
    __syncthreads();

    for (int t = 0; t < KT; t++) {
        const uint32_t aB = smbase + (uint32_t)((t & 1) * BUFH) * 2u;
        const uint32_t bB = aB + (uint32_t)ABUFH * 2u;
#pragma unroll
        for (int ks = 0; ks < 4; ks++) {
            const uint32_t kof = (uint32_t)(ks * 32);   // ks*16 halves
            uint32_t bf[8][2];
#pragma unroll
            for (int jj = 0; jj < 4; jj++)
                ldsm_x4(bf[2 * jj][0], bf[2 * jj][1],
                        bf[2 * jj + 1][0], bf[2 * jj + 1][1], bB + offB[jj] + kof);
            uint32_t af0[4], af1[4];
            ldsm_x4(af0[0], af0[1], af0[2], af0[3], aB + offA0 + kof);
            ldsm_x4(af1[0], af1[1], af1[2], af1[3], aB + offA1 + kof);
#pragma unroll
            for (int j = 0; j < 8; j++) {
                mma_f16(d[0][j], af0, bf[j]);
                mma_f16(d[1][j], af1, bf[j]);
            }
        }
        __syncthreads();
        if (t + 2 < KT) { ISSUE((t + 2) * KC, t & 1); CP_COMMIT(); }
        if (t + 1 < KT) {
            if (t + 2 < KT) CP_WAIT1(); else CP_WAIT0();
            __syncthreads();
        }
    }

    // ---------------- epilogue ----------------
#pragma unroll
    for (int i = 0; i < 2; i++) {
        int mr[2];
        mr[0] = m_base + wm * 32 + i * 16 + g;
        mr[1] = mr[0] + 8;
#pragma unroll
        for (int j = 0; j < 8; j++) {
            int n0 = n_base + wn * 64 + j * 8 + tq * 2;
#pragma unroll
            for (int rr = 0; rr < 2; rr++) {
                float v0 = d[i][j][rr * 2 + 0];
                float v1 = d[i][j][rr * 2 + 1];
                int m = mr[rr];
                if (MODE == 0) {
                    if (z == 3) {
                        if (n0 < 64) {
                            int r0i = n0 >> 4, d0i = n0 & 15;
                            int r1i = (n0 + 1) >> 4, d1i = (n0 + 1) & 15;
                            g_h1[(size_t)m * H1LD + r0i * DIN1 + 128 + d0i] =
                                __float2half_rn(v0 + b_in[n0]);
                            g_h1[(size_t)m * H1LD + r1i * DIN1 + 128 + d1i] =
                                __float2half_rn(v1 + b_in[n0 + 1]);
                        }
                    } else {
                        __half* C = g_qkv + (size_t)z * TOK * DIMN;
                        *(__half2*)(C + (size_t)m * DIMN + n0) =
                            __floats2half2_rn(v0 + bias[n0], v1 + bias[n0 + 1]);
                    }
                } else if (MODE == 2) {
                    float rsv = rs[m * RNUM + z];
                    size_t base = (size_t)m * HSLDP + z * INTP + n0;
                    if (n0 + 1 < INTER) {
                        *(__half2*)(g_hs + base) = __floats2half2_rn(
                            fmaxf(v0 + bias[n0], 0.f) * rsv,
                            fmaxf(v1 + bias[n0 + 1], 0.f) * rsv);
                    } else if (n0 < INTER) {
                        g_hs[base] = __float2half_rn(fmaxf(v0 + bias[n0], 0.f) * rsv);
                    }
                } else {
                    float4 q = *(const float4*)(rs + m * RNUM);
                    float b0 = q.x * bias[n0]            + q.y * bias[DIMN + n0]
                             + q.z * bias[2 * DIMN + n0] + q.w * bias[3 * DIMN + n0];
                    float b1v = q.x * bias[n0 + 1]            + q.y * bias[DIMN + n0 + 1]
                              + q.z * bias[2 * DIMN + n0 + 1] + q.w * bias[3 * DIMN + n0 + 1];
                    *(float2*)(out + (size_t)m * DIMN + n0) =
                        make_float2(v0 + b0, v1 + b1v);
                }
            }
        }
    }

    if (MODE == 3 && blockIdx.x == 0) {
        int idx = blockIdx.y * 512 + tid * 2;
        *(float2*)(out + (size_t)TOK * DIMN + idx) = *(const float2*)(rs + idx);
    }
#undef ISSUE
}

// ============================================================
// Flash attention, fp16 mma (unchanged from R9).
// ============================================================
#define LDQH 24
#define LDPH 136
#define FA_SMEM ((128 * LDQH * 2 + 16 * LDPH + 128 * LDPH) * 2)

__global__ void __launch_bounds__(256, 2) fa_kernel()
{
    extern __shared__ __half fsh[];
    __half* Qs = fsh;
    __half* Ks = fsh + 128 * LDQH;
    __half* Vs = fsh + 2 * 128 * LDQH;
    __half* Ps = Vs + 16 * LDPH;

    const int qt = blockIdx.x;
    const int gg = blockIdx.y;
    const int bb = blockIdx.z;
    const int r = gg >> 3, hh = gg & 7;
    const int tid = threadIdx.x;
    const int wid = tid >> 5, lane = tid & 31;
    const int g = lane >> 2, tq = lane & 3;

    const __half* gq = g_qkv;
    const __half* gk = g_qkv + (size_t)TOK * DIMN;
    const __half* gv = g_qkv + 2 * (size_t)TOK * DIMN;
    const int seq0 = bb * NSEQ;

    const __half2 qscale = __floats2half2_rn(0.25f, 0.25f);

    {
        int row = tid >> 1, part = tid & 1;
        int tok = seq0 + qt * 128 + row;
        uint4 v = *(const uint4*)(gq + (size_t)tok * DIMN + gg * HD + part * 8);
        __half2* pv = (__half2*)&v;
#pragma unroll
        for (int l = 0; l < 4; l++) pv[l] = __hmul2(pv[l], qscale);
        *(uint4*)(Qs + row * LDQH + part * 8) = v;
    }

    float o[2][4];
#pragma unroll
    for (int j = 0; j < 2; j++)
#pragma unroll
        for (int c = 0; c < 4; c++) o[j][c] = 0.f;
    float lsum[2] = {0.f, 0.f};

    const int row0 = wid * 16 + g;

    for (int jt = 0; jt < 4; jt++) {
        {
            int row = tid >> 1, part = tid & 1;
            int tok = seq0 + jt * 128 + row;
            uint4 kv = *(const uint4*)(gk + (size_t)tok * DIMN + gg * HD + part * 8);
            *(uint4*)(Ks + row * LDQH + part * 8) = kv;
            uint4 vv = *(const uint4*)(gv + (size_t)tok * DIMN + gg * HD + part * 8);
            __half tmp[8];
            *(uint4*)tmp = vv;
            int d0 = part * 8;
#pragma unroll
            for (int l = 0; l < 8; l++) Vs[(d0 + l) * LDPH + row] = tmp[l];
        }
        __syncthreads();

        uint32_t af[4];
        af[0] = *(const uint32_t*)(Qs + row0 * LDQH + 2 * tq);
        af[1] = *(const uint32_t*)(Qs + (row0 + 8) * LDQH + 2 * tq);
        af[2] = *(const uint32_t*)(Qs + row0 * LDQH + 8 + 2 * tq);
        af[3] = *(const uint32_t*)(Qs + (row0 + 8) * LDQH + 8 + 2 * tq);

#pragma unroll
        for (int hn = 0; hn < 2; hn++) {
            float s[8][4];
#pragma unroll
            for (int jn = 0; jn < 8; jn++) {
#pragma unroll
                for (int c = 0; c < 4; c++) s[jn][c] = 0.f;
                int col = hn * 64 + jn * 8 + g;
                uint32_t bf[2];
                bf[0] = *(const uint32_t*)(Ks + col * LDQH + 2 * tq);
                bf[1] = *(const uint32_t*)(Ks + col * LDQH + 8 + 2 * tq);
                mma_f16(s[jn], af, bf);
            }
#pragma unroll
            for (int jn = 0; jn < 8; jn++) {
                int c0 = hn * 64 + jn * 8 + 2 * tq;
                int gc0 = jt * 128 + c0;
#pragma unroll
                for (int rr = 0; rr < 2; rr++) {
                    int rl = row0 + rr * 8;
                    int grow = qt * 128 + rl;
                    float p0 = fast_exp(s[jn][rr * 2 + 0]);
                    float p1 = fast_exp(s[jn][rr * 2 + 1]);
                    if (gc0 == grow)     p0 = 0.f;
                    if (gc0 + 1 == grow) p1 = 0.f;
                    lsum[rr] += p0 + p1;
                    *(__half2*)(Ps + rl * LDPH + c0) = __floats2half2_rn(p0, p1);
                }
            }
        }
        __syncthreads();

#pragma unroll
        for (int ksi = 0; ksi < 8; ksi++) {
            uint32_t pa[4];
            pa[0] = *(const uint32_t*)(Ps + row0 * LDPH + ksi * 16 + 2 * tq);
            pa[1] = *(const uint32_t*)(Ps + (row0 + 8) * LDPH + ksi * 16 + 2 * tq);
            pa[2] = *(const uint32_t*)(Ps + row0 * LDPH + ksi * 16 + 8 + 2 * tq);
            pa[3] = *(const uint32_t*)(Ps + (row0 + 8) * LDPH + ksi * 16 + 8 + 2 * tq);
#pragma unroll
            for (int jn = 0; jn < 2; jn++) {
                int col = jn * 8 + g;
                uint32_t bf[2];
                bf[0] = *(const uint32_t*)(Vs + col * LDPH + ksi * 16 + 2 * tq);
                bf[1] = *(const uint32_t*)(Vs + col * LDPH + ksi * 16 + 8 + 2 * tq);
                mma_f16(o[jn], pa, bf);
            }
        }
        __syncthreads();
    }

#pragma unroll
    for (int rr = 0; rr < 2; rr++) {
        lsum[rr] += __shfl_xor_sync(0xFFFFFFFF, lsum[rr], 1);
        lsum[rr] += __shfl_xor_sync(0xFFFFFFFF, lsum[rr], 2);
    }
    float inv[2] = {1.f / lsum[0], 1.f / lsum[1]};

#pragma unroll
    for (int rr = 0; rr < 2; rr++) {
        int tok = seq0 + qt * 128 + row0 + rr * 8;
        __half* dst = g_h1 + (size_t)tok * H1LD + r * DIN1 + hh * HD;
#pragma unroll
        for (int jn = 0; jn < 2; jn++) {
            int col = jn * 8 + 2 * tq;
            *(__half2*)(dst + col) = __floats2half2_rn(o[jn][rr * 2 + 0] * inv[rr],
                                                       o[jn][rr * 2 + 1] * inv[rr]);
        }
    }
}

// ============================================================
extern "C" void kernel_launch(void* const* d_in, const int* in_sizes, int n_in,
                              void* d_out, int out_size)
{
    const float* x    = (const float*)d_in[0];
    const float* rs   = (const float*)d_in[1];
    const float* Wq   = (const float*)d_in[2];
    const float* bq   = (const float*)d_in[3];
    const float* Wk   = (const float*)d_in[4];
    const float* bk   = (const float*)d_in[5];
    const float* Wv   = (const float*)d_in[6];
    const float* bv   = (const float*)d_in[7];
    const float* Win  = (const float*)d_in[8];
    const float* b_in = (const float*)d_in[9];
    const float* W1   = (const float*)d_in[10];
    const float* b1   = (const float*)d_in[11];
    const float* W2   = (const float*)d_in[12];
    const float* b2   = (const float*)d_in[13];
    float* out = (float*)d_out;

    cudaFuncSetAttribute(mma_gemm<0>, cudaFuncAttributeMaxDynamicSharedMemorySize, GEMM_SMEM);
    cudaFuncSetAttribute(mma_gemm<2>, cudaFuncAttributeMaxDynamicSharedMemorySize, GEMM_SMEM);
    cudaFuncSetAttribute(mma_gemm<3>, cudaFuncAttributeMaxDynamicSharedMemorySize, GEMM_SMEM);
    cudaFuncSetAttribute(fa_kernel, cudaFuncAttributeMaxDynamicSharedMemorySize, FA_SMEM);

    conv_all<<<2132, 256>>>(x, Wq, Wk, Wv, Win, W1, W2);

    mma_gemm<0><<<dim3(4, 32, 4), 256, GEMM_SMEM>>>(bq, bk, bv, b_in, b1, b2, rs, out);
    fa_kernel<<<dim3(4, GQ, 8), 256, FA_SMEM>>>();
    mma_gemm<2><<<dim3(4, 32, 4), 256, GEMM_SMEM>>>(bq, bk, bv, b_in, b1, b2, rs, out);
    mma_gemm<3><<<dim3(4, 32, 1), 256, GEMM_SMEM>>>(bq, bk, bv, b_in, b1, b2, rs, out);
}

// round 11
// speedup vs baseline: 2.3341x; 1.1894x over previous
#include <cuda_runtime.h>
#include <cuda_fp16.h>
#include <cstdint>

#define TOK   4096
#define DIMN  512
#define GQ    32
#define HD    16
#define RNUM  4
#define INTER 405
#define INTP  408
#define DIN1  144
#define H1LD  576
#define HSLDP 1632
#define NSEQ  512

// ---------------- device scratch (fp16 payloads) ----------------
__device__ __half g_xc[TOK * DIMN];
__device__ __half g_wqt[DIMN * DIMN];     // [n][k]
__device__ __half g_wkt[DIMN * DIMN];
__device__ __half g_wvt[DIMN * DIMN];
__device__ __half g_wint[64 * DIMN];
__device__ __half g_w1t[RNUM * INTP * DIN1];   // per rule [408][144]
__device__ __half g_w2t[DIMN * HSLDP];         // [512][1632], pad k zero
__device__ __half g_qkv[3 * TOK * DIMN];
__device__ __half g_h1[TOK * H1LD];
__device__ __half g_hs[TOK * HSLDP];

// ---------------- helpers ----------------
__device__ __forceinline__ uint32_t smem_u32(const void* p) {
    uint32_t a;
    asm("{ .reg .u64 t; cvta.to.shared.u64 t, %1; cvt.u32.u64 %0, t; }"
        : "=r"(a) : "l"(p));
    return a;
}
__device__ __forceinline__ void cp16(uint32_t dst, const void* src, bool pred) {
    int sz = pred ? 16 : 0;
    asm volatile("cp.async.ca.shared.global [%0], [%1], 16, %2;"
                 :: "r"(dst), "l"(src), "r"(sz) : "memory");
}
#define CP_COMMIT() asm volatile("cp.async.commit_group;" ::: "memory")
#define CP_WAIT1()  asm volatile("cp.async.wait_group 1;" ::: "memory")
#define CP_WAIT0()  asm volatile("cp.async.wait_group 0;" ::: "memory")

__device__ __forceinline__ void mma_f16(float d[4], const uint32_t a[4],
                                        const uint32_t b[2]) {
    asm volatile(
        "mma.sync.aligned.m16n8k16.row.col.f32.f16.f16.f32 "
        "{%0,%1,%2,%3}, {%4,%5,%6,%7}, {%8,%9}, {%0,%1,%2,%3};"
        : "+f"(d[0]), "+f"(d[1]), "+f"(d[2]), "+f"(d[3])
        : "r"(a[0]), "r"(a[1]), "r"(a[2]), "r"(a[3]), "r"(b[0]), "r"(b[1]));
}
__device__ __forceinline__ void ldsm_x4(uint32_t& r0, uint32_t& r1,
                                        uint32_t& r2, uint32_t& r3, uint32_t addr) {
    asm volatile("ldmatrix.sync.aligned.m8n8.x4.shared.b16 {%0,%1,%2,%3}, [%4];"
                 : "=r"(r0), "=r"(r1), "=r"(r2), "=r"(r3) : "r"(addr));
}
// single-MUFU exp2 (scores already in log2 units)
__device__ __forceinline__ float ex2(float s) {
    float r;
    asm("ex2.approx.f32 %0, %1;" : "=f"(r) : "f"(s));
    return r;
}

// ---------------- one-shot conversion + weight transposes ----------------
__device__ void trans_tile(const float* __restrict__ src, __half* __restrict__ dst,
                           int K, int N, int ldk, int tk, int tn, bool w2remap)
{
    __shared__ float tl[32][33];
    int tx = threadIdx.x & 31, ty = threadIdx.x >> 5;
    int k0 = tk * 32, n0 = tn * 32;
#pragma unroll
    for (int i = 0; i < 4; i++) {
        int k = k0 + ty + i * 8, n = n0 + tx;
        tl[ty + i * 8][tx] = (k < K && n < N) ? src[(size_t)k * N + n] : 0.f;
    }
    __syncthreads();
#pragma unroll
    for (int i = 0; i < 4; i++) {
        int n = n0 + ty + i * 8, k = k0 + tx;
        if (n < N && k < K) {
            int kk = w2remap ? k + 3 * (k / 405) : k;
            dst[(size_t)n * ldk + kk] = __float2half_rn(tl[tx][ty + i * 8]);
        }
    }
}

__global__ void conv_all(const float* __restrict__ x,  const float* __restrict__ Wq,
                         const float* __restrict__ Wk, const float* __restrict__ Wv,
                         const float* __restrict__ Win, const float* __restrict__ W1,
                         const float* __restrict__ W2)
{
    int b = blockIdx.x;
    if (b < 256) {
#pragma unroll
        for (int u = 0; u < 32; u++) {
            int i = b * 8192 + u * 256 + threadIdx.x;
            g_xc[i] = __float2half_rn(x[i]);
        }
    } else if (b < 512) {
        int i = b - 256;  trans_tile(Wq, g_wqt, 512, 512, 512, i / 16, i % 16, false);
    } else if (b < 768) {
        int i = b - 512;  trans_tile(Wk, g_wkt, 512, 512, 512, i / 16, i % 16, false);
    } else if (b < 1024) {
        int i = b - 768;  trans_tile(Wv, g_wvt, 512, 512, 512, i / 16, i % 16, false);
    } else if (b < 1056) {
        int i = b - 1024; trans_tile(Win, g_wint, 512, 64, 512, i / 2, i % 2, false);
    } else if (b < 1316) {
        int i = b - 1056; int r = i / 65, rem = i % 65;
        trans_tile(W1 + (size_t)r * DIN1 * INTER, g_w1t + (size_t)r * INTP * DIN1,
                   DIN1, INTER, DIN1, rem / 13, rem % 13, false);
    } else {
        int i = b - 1316;
        trans_tile(W2, g_w2t, 1620, 512, HSLDP, i / 16, i % 16, true);
    }
}

// ============================================================
// fp16 mma GEMM (unchanged from R10): CTA 128x128, KC=64, 8 warps,
// warp tile 32x64, 2-stage cp.async + ldmatrix.x4 fragment loads.
// ============================================================
#define KC     64
#define LDH    72
#define ABUFH  (128 * LDH)
#define BBUFH  (128 * LDH)
#define BUFH   (ABUFH + BBUFH)
#define GEMM_SMEM (2 * BUFH * 2)

template<int MODE>
__global__ void __launch_bounds__(256, 2) mma_gemm(
    const float* __restrict__ bq, const float* __restrict__ bk,
    const float* __restrict__ bv, const float* __restrict__ b_in,
    const float* __restrict__ b1, const float* __restrict__ b2,
    const float* __restrict__ rs, float* __restrict__ out)
{
    extern __shared__ __half dynsh[];
    const uint32_t smbase = smem_u32(dynsh);

    const int tid = threadIdx.x;
    const int wid = tid >> 5, lane = tid & 31;
    const int wm = wid >> 1, wn = wid & 1;
    const int g = lane >> 2, tq = lane & 3;
    const int m_base = blockIdx.y * 128;
    const int n_base = blockIdx.x * 128;
    const int z = blockIdx.z;

    const __half* A; const __half* Bt; const float* bias;
    int lda, K, Nrows, ldbk;
    if (MODE == 0) {
        A = g_xc + (size_t)m_base * DIMN; lda = DIMN; K = DIMN;
        if (z == 3) {
            if (blockIdx.x != 0) return;
            Bt = g_wint; Nrows = 64; ldbk = DIMN; bias = b_in;
        } else {
            Bt = (z == 0) ? g_wqt : (z == 1) ? g_wkt : g_wvt;
            Nrows = 512; ldbk = DIMN;
            bias = (z == 0) ? bq : (z == 1) ? bk : bv;
        }
    }
    if (MODE == 2) {
        A = g_h1 + (size_t)m_base * H1LD + z * DIN1; lda = H1LD; K = DIN1;
        Bt = g_w1t + (size_t)z * INTP * DIN1; Nrows = INTP; ldbk = DIN1;
        bias = b1 + z * INTER;
    }
    if (MODE == 3) {
        A = g_hs + (size_t)m_base * HSLDP; lda = HSLDP; K = HSLDP;
        Bt = g_w2t; Nrows = 512; ldbk = HSLDP; bias = b2;
    }

    float d[2][8][4];
#pragma unroll
    for (int i = 0; i < 2; i++)
#pragma unroll
        for (int j = 0; j < 8; j++)
#pragma unroll
            for (int c = 0; c < 4; c++) d[i][j][c] = 0.f;

    const int KT = (K + KC - 1) / KC;

    const int l8 = lane & 7, lm = lane >> 3;
    const uint32_t offA0 = (uint32_t)(((wm * 32 + (lm & 1) * 8 + l8) * LDH
                                       + (lm >> 1) * 8) * 2);
    const uint32_t offA1 = offA0 + (uint32_t)(16 * LDH * 2);
    uint32_t offB[4];
#pragma unroll
    for (int jj = 0; jj < 4; jj++)
        offB[jj] = (uint32_t)(((wn * 64 + jj * 16 + (lm >> 1) * 8 + l8) * LDH
                               + (lm & 1) * 8) * 2);

#define ISSUE(k0, buf)                                                         \
    do {                                                                       \
        uint32_t sA = smbase + (uint32_t)((buf) * BUFH) * 2u;                  \
        uint32_t sB = sA + (uint32_t)ABUFH * 2u;                               \
        _Pragma("unroll")                                                      \
        for (int i = 0; i < 4; i++) {                                          \
            int idx = tid + (i << 8);                                          \
            int row = idx >> 3, grp = idx & 7;                                 \
            int kk = (k0) + grp * 8;                                           \
            bool pk = kk < K;                                                  \
            int kcl = pk ? kk : 0;                                             \
            cp16(sA + (uint32_t)(row * LDH + grp * 8) * 2u,                    \
                 A + (size_t)row * lda + kcl, pk);                             \
            bool pb = pk && (n_base + row) < Nrows;                            \
            int brow = ((n_base + row) < Nrows) ? (n_base + row) : 0;          \
            cp16(sB + (uint32_t)(row * LDH + grp * 8) * 2u,                    \
                 Bt + (size_t)brow * ldbk + kcl, pb);                          \
        }                                                                      \
    } while (0)

    ISSUE(0, 0);
    CP_COMMIT();
    ISSUE(KC, 1);
    CP_COMMIT();
    CP_WAIT1();
    __syncthreads();

    for (int t = 0; t < KT; t++) {
        const uint32_t aB = smbase + (uint32_t)((t & 1) * BUFH) * 2u;
        const uint32_t bB = aB + (uint32_t)ABUFH * 2u;
#pragma unroll
        for (int ks = 0; ks < 4; ks++) {
            const uint32_t kof = (uint32_t)(ks * 32);
            uint32_t bf[8][2];
#pragma unroll
            for (int jj = 0; jj < 4; jj++)
                ldsm_x4(bf[2 * jj][0], bf[2 * jj][1],
                        bf[2 * jj + 1][0], bf[2 * jj + 1][1], bB + offB[jj] + kof);
            uint32_t af0[4], af1[4];
            ldsm_x4(af0[0], af0[1], af0[2], af0[3], aB + offA0 + kof);
            ldsm_x4(af1[0], af1[1], af1[2], af1[3], aB + offA1 + kof);
#pragma unroll
            for (int j = 0; j < 8; j++) {
                mma_f16(d[0][j], af0, bf[j]);
                mma_f16(d[1][j], af1, bf[j]);
            }
        }
        __syncthreads();
        if (t + 2 < KT) { ISSUE((t + 2) * KC, t & 1); CP_COMMIT(); }
        if (t + 1 < KT) {
            if (t + 2 < KT) CP_WAIT1(); else CP_WAIT0();
            __syncthreads();
        }
    }

    // ---------------- epilogue ----------------
#pragma unroll
    for (int i = 0; i < 2; i++) {
        int mr[2];
        mr[0] = m_base + wm * 32 + i * 16 + g;
        mr[1] = mr[0] + 8;
#pragma unroll
        for (int j = 0; j < 8; j++) {
            int n0 = n_base + wn * 64 + j * 8 + tq * 2;
#pragma unroll
            for (int rr = 0; rr < 2; rr++) {
                float v0 = d[i][j][rr * 2 + 0];
                float v1 = d[i][j][rr * 2 + 1];
                int m = mr[rr];
                if (MODE == 0) {
                    if (z == 3) {
                        if (n0 < 64) {
                            int r0i = n0 >> 4, d0i = n0 & 15;
                            int r1i = (n0 + 1) >> 4, d1i = (n0 + 1) & 15;
                            g_h1[(size_t)m * H1LD + r0i * DIN1 + 128 + d0i] =
                                __float2half_rn(v0 + b_in[n0]);
                            g_h1[(size_t)m * H1LD + r1i * DIN1 + 128 + d1i] =
                                __float2half_rn(v1 + b_in[n0 + 1]);
                        }
                    } else {
                        __half* C = g_qkv + (size_t)z * TOK * DIMN;
                        *(__half2*)(C + (size_t)m * DIMN + n0) =
                            __floats2half2_rn(v0 + bias[n0], v1 + bias[n0 + 1]);
                    }
                } else if (MODE == 2) {
                    float rsv = rs[m * RNUM + z];
                    size_t base = (size_t)m * HSLDP + z * INTP + n0;
                    if (n0 + 1 < INTER) {
                        *(__half2*)(g_hs + base) = __floats2half2_rn(
                            fmaxf(v0 + bias[n0], 0.f) * rsv,
                            fmaxf(v1 + bias[n0 + 1], 0.f) * rsv);
                    } else if (n0 < INTER) {
                        g_hs[base] = __float2half_rn(fmaxf(v0 + bias[n0], 0.f) * rsv);
                    }
                } else {
                    float4 q = *(const float4*)(rs + m * RNUM);
                    float b0 = q.x * bias[n0]            + q.y * bias[DIMN + n0]
                             + q.z * bias[2 * DIMN + n0] + q.w * bias[3 * DIMN + n0];
                    float b1v = q.x * bias[n0 + 1]            + q.y * bias[DIMN + n0 + 1]
                              + q.z * bias[2 * DIMN + n0 + 1] + q.w * bias[3 * DIMN + n0 + 1];
                    *(float2*)(out + (size_t)m * DIMN + n0) =
                        make_float2(v0 + b0, v1 + b1v);
                }
            }
        }
    }

    if (MODE == 3 && blockIdx.x == 0) {
        int idx = blockIdx.y * 512 + tid * 2;
        *(float2*)(out + (size_t)TOK * DIMN + idx) = *(const float2*)(rs + idx);
    }
#undef ISSUE
}

// ============================================================
// Flash attention, fp16 mma. Changes this round:
//  - exp -> single-MUFU ex2.approx; log2(e) folded into Q pre-scale
//  - all fragment loads via ldmatrix.x4 (Q, K, P, V)
// ============================================================
#define LDQH 24
#define LDPH 136
#define FA_SMEM ((128 * LDQH * 2 + 16 * LDPH + 128 * LDPH) * 2)
#define QK_SCALE 0.360673760222241f   /* 0.25 * log2(e) */

__global__ void __launch_bounds__(256, 2) fa_kernel()
{
    extern __shared__ __half fsh[];
    __half* Qs = fsh;
    __half* Ks = fsh + 128 * LDQH;
    __half* Vs = fsh + 2 * 128 * LDQH;
    __half* Ps = Vs + 16 * LDPH;
    const uint32_t uQs = smem_u32(Qs);
    const uint32_t uKs = smem_u32(Ks);
    const uint32_t uVs = smem_u32(Vs);
    const uint32_t uPs = smem_u32(Ps);

    const int qt = blockIdx.x;
    const int gg = blockIdx.y;
    const int bb = blockIdx.z;
    const int r = gg >> 3, hh = gg & 7;
    const int tid = threadIdx.x;
    const int wid = tid >> 5, lane = tid & 31;
    const int g = lane >> 2, tq = lane & 3;
    const int l8 = lane & 7, lm = lane >> 3;

    const __half* gq = g_qkv;
    const __half* gk = g_qkv + (size_t)TOK * DIMN;
    const __half* gv = g_qkv + 2 * (size_t)TOK * DIMN;
    const int seq0 = bb * NSEQ;

    const __half2 qscale = __floats2half2_rn(QK_SCALE, QK_SCALE);

    {   // Q tile (pre-scaled by 0.25*log2e -> scores in log2 units)
        int row = tid >> 1, part = tid & 1;
        int tok = seq0 + qt * 128 + row;
        uint4 v = *(const uint4*)(gq + (size_t)tok * DIMN + gg * HD + part * 8);
        __half2* pv = (__half2*)&v;
#pragma unroll
        for (int l = 0; l < 4; l++) pv[l] = __hmul2(pv[l], qscale);
        *(uint4*)(Qs + row * LDQH + part * 8) = v;
    }

    float o[2][4];
#pragma unroll
    for (int j = 0; j < 2; j++)
#pragma unroll
        for (int c = 0; c < 4; c++) o[j][c] = 0.f;
    float lsum[2] = {0.f, 0.f};

    const int row0 = wid * 16 + g;

    // ldmatrix offsets
    const uint32_t offQA = (uint32_t)(((wid * 16 + (lm & 1) * 8 + l8) * LDQH
                                       + (lm >> 1) * 8) * 2);
    uint32_t offKB[4];   // per hn add hn*64*LDQH*2
#pragma unroll
    for (int jj = 0; jj < 4; jj++)
        offKB[jj] = (uint32_t)(((jj * 16 + (lm >> 1) * 8 + l8) * LDQH
                                + (lm & 1) * 8) * 2);
    const uint32_t offPA = (uint32_t)(((wid * 16 + (lm & 1) * 8 + l8) * LDPH
                                       + (lm >> 1) * 8) * 2);
    const uint32_t offVB = (uint32_t)((((lm >> 1) * 8 + l8) * LDPH
                                       + (lm & 1) * 8) * 2);

    for (int jt = 0; jt < 4; jt++) {
        {   // K, V tiles
            int row = tid >> 1, part = tid & 1;
            int tok = seq0 + jt * 128 + row;
            uint4 kv = *(const uint4*)(gk + (size_t)tok * DIMN + gg * HD + part * 8);
            *(uint4*)(Ks + row * LDQH + part * 8) = kv;
            uint4 vv = *(const uint4*)(gv + (size_t)tok * DIMN + gg * HD + part * 8);
            __half tmp[8];
            *(uint4*)tmp = vv;
            int d0 = part * 8;
#pragma unroll
            for (int l = 0; l < 8; l++) Vs[(d0 + l) * LDPH + row] = tmp[l];
        }
        __syncthreads();

        uint32_t af[4];
        ldsm_x4(af[0], af[1], af[2], af[3], uQs + offQA);

#pragma unroll
        for (int hn = 0; hn < 2; hn++) {
            const uint32_t hof = (uint32_t)(hn * 64 * LDQH * 2);
            uint32_t bf[8][2];
#pragma unroll
            for (int jj = 0; jj < 4; jj++)
                ldsm_x4(bf[2 * jj][0], bf[2 * jj][1],
                        bf[2 * jj + 1][0], bf[2 * jj + 1][1],
                        uKs + offKB[jj] + hof);
            float s[8][4];
#pragma unroll
            for (int jn = 0; jn < 8; jn++) {
#pragma unroll
                for (int c = 0; c < 4; c++) s[jn][c] = 0.f;
                mma_f16(s[jn], af, bf[jn]);
            }
#pragma unroll
            for (int jn = 0; jn < 8; jn++) {
                int c0 = hn * 64 + jn * 8 + 2 * tq;
                int gc0 = jt * 128 + c0;
#pragma unroll
                for (int rr = 0; rr < 2; rr++) {
                    int rl = row0 + rr * 8;
                    int grow = qt * 128 + rl;
                    float p0 = ex2(s[jn][rr * 2 + 0]);
                    float p1 = ex2(s[jn][rr * 2 + 1]);
                    if (gc0 == grow)     p0 = 0.f;
                    if (gc0 + 1 == grow) p1 = 0.f;
                    lsum[rr] += p0 + p1;
                    *(__half2*)(Ps + rl * LDPH + c0) = __floats2half2_rn(p0, p1);
                }
            }
        }
        __syncthreads();

        // O += P @ V
#pragma unroll
        for (int ksi = 0; ksi < 8; ksi++) {
            const uint32_t kof = (uint32_t)(ksi * 32);
            uint32_t pa[4];
            ldsm_x4(pa[0], pa[1], pa[2], pa[3], uPs + offPA + kof);
            uint32_t bf[2][2];
            ldsm_x4(bf[0][0], bf[0][1], bf[1][0], bf[1][1], uVs + offVB + kof);
            mma_f16(o[0], pa, bf[0]);
            mma_f16(o[1], pa, bf[1]);
        }
        __syncthreads();
    }

#pragma unroll
    for (int rr = 0; rr < 2; rr++) {
        lsum[rr] += __shfl_xor_sync(0xFFFFFFFF, lsum[rr], 1);
        lsum[rr] += __shfl_xor_sync(0xFFFFFFFF, lsum[rr], 2);
    }
    float inv[2] = {1.f / lsum[0], 1.f / lsum[1]};

#pragma unroll
    for (int rr = 0; rr < 2; rr++) {
        int tok = seq0 + qt * 128 + row0 + rr * 8;
        __half* dst = g_h1 + (size_t)tok * H1LD + r * DIN1 + hh * HD;
#pragma unroll
        for (int jn = 0; jn < 2; jn++) {
            int col = jn * 8 + 2 * tq;
            *(__half2*)(dst + col) = __floats2half2_rn(o[jn][rr * 2 + 0] * inv[rr],
                                                       o[jn][rr * 2 + 1] * inv[rr]);
        }
    }
}

// ============================================================
extern "C" void kernel_launch(void* const* d_in, const int* in_sizes, int n_in,
                              void* d_out, int out_size)
{
    const float* x    = (const float*)d_in[0];
    const float* rs   = (const float*)d_in[1];
    const float* Wq   = (const float*)d_in[2];
    const float* bq   = (const float*)d_in[3];
    const float* Wk   = (const float*)d_in[4];
    const float* bk   = (const float*)d_in[5];
    const float* Wv   = (const float*)d_in[6];
    const float* bv   = (const float*)d_in[7];
    const float* Win  = (const float*)d_in[8];
    const float* b_in = (const float*)d_in[9];
    const float* W1   = (const float*)d_in[10];
    const float* b1   = (const float*)d_in[11];
    const float* W2   = (const float*)d_in[12];
    const float* b2   = (const float*)d_in[13];
    float* out = (float*)d_out;

    cudaFuncSetAttribute(mma_gemm<0>, cudaFuncAttributeMaxDynamicSharedMemorySize, GEMM_SMEM);
    cudaFuncSetAttribute(mma_gemm<2>, cudaFuncAttributeMaxDynamicSharedMemorySize, GEMM_SMEM);
    cudaFuncSetAttribute(mma_gemm<3>, cudaFuncAttributeMaxDynamicSharedMemorySize, GEMM_SMEM);
    cudaFuncSetAttribute(fa_kernel, cudaFuncAttributeMaxDynamicSharedMemorySize, FA_SMEM);

    conv_all<<<2132, 256>>>(x, Wq, Wk, Wv, Win, W1, W2);

    mma_gemm<0><<<dim3(4, 32, 4), 256, GEMM_SMEM>>>(bq, bk, bv, b_in, b1, b2, rs, out);
    fa_kernel<<<dim3(4, GQ, 8), 256, FA_SMEM>>>();
    mma_gemm<2><<<dim3(4, 32, 4), 256, GEMM_SMEM>>>(bq, bk, bv, b_in, b1, b2, rs, out);
    mma_gemm<3><<<dim3(4, 32, 1), 256, GEMM_SMEM>>>(bq, bk, bv, b_in, b1, b2, rs, out);
}